// round 13
// baseline (speedup 1.0000x reference)
#include <cuda_runtime.h>
#include <cuda_bf16.h>
#include <cstdint>

#define SQ   4096
#define BHN  64
#define PB   68     // fp32 smem pitch (floats)
#define PW   36     // packed bf16x2 word pitch
#define NSP  16     // kc blocks per bh
#define NS2  32     // softmax splits (2 per kc block)

typedef unsigned long long u64t;
typedef unsigned int u32;

// ---------------- scratch ----------------
__device__ float g_Qlm [BHN*64*64];
__device__ float g_KlmT[BHN*64*64];
__device__ float g_Klm [BHN*64*64];
__device__ float g_Inv [BHN*64*64];
__device__ float g_WT  [BHN*64*64];   // (inv@F)^T : [d][m]
__device__ float g_pacc[(size_t)NS2*BHN*64*64];
__device__ float g_psum[NS2*BHN*64];

// ---------------- scalar helpers ----------------
__device__ __forceinline__ u64t pk2(float lo, float hi) {
    u64t r; asm("mov.b64 %0, {%1, %2};" : "=l"(r) : "f"(lo), "f"(hi)); return r;
}
__device__ __forceinline__ u64t ffma2(u64t a, u64t b, u64t c) {
    u64t d; asm("fma.rn.f32x2 %0, %1, %2, %3;" : "=l"(d) : "l"(a), "l"(b), "l"(c)); return d;
}
__device__ __forceinline__ u32 bfpack(float x, float y) {
    __nv_bfloat162 h = __floats2bfloat162_rn(x, y);
    return *reinterpret_cast<u32*>(&h);
}
__device__ __forceinline__ void bfsplit(float x, float y, u32& hw, u32& lw) {
    __nv_bfloat162 h = __floats2bfloat162_rn(x, y);
    float hx = __bfloat162float(h.x), hy = __bfloat162float(h.y);
    hw = *reinterpret_cast<u32*>(&h);
    lw = bfpack(x - hx, y - hy);
}
__device__ __forceinline__ void mmab(float c[4], u32 a0, u32 a1, u32 a2, u32 a3,
                                     u32 b0, u32 b1) {
    asm volatile("mma.sync.aligned.m16n8k16.row.col.f32.bf16.bf16.f32 "
        "{%0,%1,%2,%3}, {%4,%5,%6,%7}, {%8,%9}, {%0,%1,%2,%3};"
        : "+f"(c[0]), "+f"(c[1]), "+f"(c[2]), "+f"(c[3])
        : "r"(a0), "r"(a1), "r"(a2), "r"(a3), "r"(b0), "r"(b1));
}
__device__ __forceinline__ u32 sptr(const void* p) {
    u32 a;
    asm("{ .reg .u64 t; cvta.to.shared.u64 t, %1; cvt.u32.u64 %0, t; }" : "=r"(a) : "l"(p));
    return a;
}
__device__ __forceinline__ void ldsm4(u32* r, u32 addr) {
    asm volatile("ldmatrix.sync.aligned.m8n8.x4.shared.b16 {%0,%1,%2,%3}, [%4];"
        : "=r"(r[0]), "=r"(r[1]), "=r"(r[2]), "=r"(r[3]) : "r"(addr));
}

// warp gemm: C[16x64] += A[16 rows, k=64] @ B[64 n, k=64]  (kd MMA1)
__device__ __forceinline__ void wgemm16(const u32* __restrict__ Ah, const u32* __restrict__ Al,
                                        int base,
                                        const u32* __restrict__ Bh, const u32* __restrict__ Bl,
                                        int lane, float c[8][4]) {
    int mi = lane >> 3, lr = lane & 7;
    u32 aH = sptr(Ah + (base + (mi & 1)*8 + lr)*PW + (mi >> 1)*4);
    u32 aL = sptr(Al + (base + (mi & 1)*8 + lr)*PW + (mi >> 1)*4);
    u32 bH = sptr(Bh + ((mi >> 1)*8 + lr)*PW + (mi & 1)*4);
    u32 bL = sptr(Bl + ((mi >> 1)*8 + lr)*PW + (mi & 1)*4);
#pragma unroll
    for (int kt = 0; kt < 4; kt++) {
        u32 ah[4], al[4];
        ldsm4(ah, aH + kt*32);
        ldsm4(al, aL + kt*32);
#pragma unroll
        for (int p = 0; p < 4; p++) {
            u32 bh[4], bl[4];
            ldsm4(bh, bH + p*(16*PW*4) + kt*32);
            ldsm4(bl, bL + p*(16*PW*4) + kt*32);
            mmab(c[2*p],   ah[0],ah[1],ah[2],ah[3], bh[0],bh[1]);
            mmab(c[2*p],   al[0],al[1],al[2],al[3], bh[0],bh[1]);
            mmab(c[2*p],   ah[0],ah[1],ah[2],ah[3], bl[0],bl[1]);
            mmab(c[2*p+1], ah[0],ah[1],ah[2],ah[3], bh[2],bh[3]);
            mmab(c[2*p+1], al[0],al[1],al[2],al[3], bh[2],bh[3]);
            mmab(c[2*p+1], ah[0],ah[1],ah[2],ah[3], bl[2],bl[3]);
        }
    }
}

// warp gemm: C[16x32] += A[16 rows, k=64] @ B[n = nbase..+31, k=64]  (kc MMA1)
__device__ __forceinline__ void wg16x32(const u32* __restrict__ Ah, const u32* __restrict__ Al,
                                        int base,
                                        const u32* __restrict__ Bh, const u32* __restrict__ Bl,
                                        int nbase, int lane, float c[4][4]) {
    int mi = lane >> 3, lr = lane & 7;
    u32 aH = sptr(Ah + (base + (mi & 1)*8 + lr)*PW + (mi >> 1)*4);
    u32 aL = sptr(Al + (base + (mi & 1)*8 + lr)*PW + (mi >> 1)*4);
    u32 bH = sptr(Bh + (nbase + (mi >> 1)*8 + lr)*PW + (mi & 1)*4);
    u32 bL = sptr(Bl + (nbase + (mi >> 1)*8 + lr)*PW + (mi & 1)*4);
#pragma unroll
    for (int kt = 0; kt < 4; kt++) {
        u32 ah[4], al[4];
        ldsm4(ah, aH + kt*32);
        ldsm4(al, aL + kt*32);
#pragma unroll
        for (int p = 0; p < 2; p++) {
            u32 bh[4], bl[4];
            ldsm4(bh, bH + p*(16*PW*4) + kt*32);
            ldsm4(bl, bL + p*(16*PW*4) + kt*32);
            mmab(c[2*p],   ah[0],ah[1],ah[2],ah[3], bh[0],bh[1]);
            mmab(c[2*p],   al[0],al[1],al[2],al[3], bh[0],bh[1]);
            mmab(c[2*p],   ah[0],ah[1],ah[2],ah[3], bl[0],bl[1]);
            mmab(c[2*p+1], ah[0],ah[1],ah[2],ah[3], bh[2],bh[3]);
            mmab(c[2*p+1], al[0],al[1],al[2],al[3], bh[2],bh[3]);
            mmab(c[2*p+1], ah[0],ah[1],ah[2],ah[3], bl[2],bl[3]);
        }
    }
}

// MMA2 from register P (kd): d[16x64] += P(c regs, k=64) @ B[64 n, k=64]
__device__ __forceinline__ void wgemm16_regA(const float c[8][4],
                                             const u32* __restrict__ Bh,
                                             const u32* __restrict__ Bl,
                                             int lane, float d[8][4]) {
    int mi = lane >> 3, lr = lane & 7;
    u32 bH = sptr(Bh + ((mi >> 1)*8 + lr)*PW + (mi & 1)*4);
    u32 bL = sptr(Bl + ((mi >> 1)*8 + lr)*PW + (mi & 1)*4);
#pragma unroll
    for (int kt = 0; kt < 4; kt++) {
        u32 ah0, al0, ah1, al1, ah2, al2, ah3, al3;
        bfsplit(c[2*kt][0],   c[2*kt][1],   ah0, al0);   // (row g,   k 2t..2t+1)
        bfsplit(c[2*kt][2],   c[2*kt][3],   ah1, al1);   // (row g+8, k 2t..2t+1)
        bfsplit(c[2*kt+1][0], c[2*kt+1][1], ah2, al2);   // (row g,   k 8+2t..)
        bfsplit(c[2*kt+1][2], c[2*kt+1][3], ah3, al3);   // (row g+8, k 8+2t..)
#pragma unroll
        for (int p = 0; p < 4; p++) {
            u32 bh[4], bl[4];
            ldsm4(bh, bH + p*(16*PW*4) + kt*32);
            ldsm4(bl, bL + p*(16*PW*4) + kt*32);
            mmab(d[2*p],   ah0,ah1,ah2,ah3, bh[0],bh[1]);
            mmab(d[2*p],   al0,al1,al2,al3, bh[0],bh[1]);
            mmab(d[2*p],   ah0,ah1,ah2,ah3, bl[0],bl[1]);
            mmab(d[2*p+1], ah0,ah1,ah2,ah3, bh[2],bh[3]);
            mmab(d[2*p+1], al0,al1,al2,al3, bh[2],bh[3]);
            mmab(d[2*p+1], ah0,ah1,ah2,ah3, bl[2],bl[3]);
        }
    }
}

// MMA2 from register P (kc): d[16x64] += P(c regs, k=32 local) @ B[64 n, k=32 at word off co]
__device__ __forceinline__ void wg_regA_k32(const float c[4][4],
                                            const u32* __restrict__ Bh,
                                            const u32* __restrict__ Bl, int co,
                                            int lane, float d[8][4]) {
    int mi = lane >> 3, lr = lane & 7;
    u32 bH = sptr(Bh + ((mi >> 1)*8 + lr)*PW + (mi & 1)*4 + co);
    u32 bL = sptr(Bl + ((mi >> 1)*8 + lr)*PW + (mi & 1)*4 + co);
#pragma unroll
    for (int kt = 0; kt < 2; kt++) {
        u32 ah0, al0, ah1, al1, ah2, al2, ah3, al3;
        bfsplit(c[2*kt][0],   c[2*kt][1],   ah0, al0);
        bfsplit(c[2*kt][2],   c[2*kt][3],   ah1, al1);
        bfsplit(c[2*kt+1][0], c[2*kt+1][1], ah2, al2);
        bfsplit(c[2*kt+1][2], c[2*kt+1][3], ah3, al3);
#pragma unroll
        for (int p = 0; p < 4; p++) {
            u32 bh[4], bl[4];
            ldsm4(bh, bH + p*(16*PW*4) + kt*32);
            ldsm4(bl, bL + p*(16*PW*4) + kt*32);
            mmab(d[2*p],   ah0,ah1,ah2,ah3, bh[0],bh[1]);
            mmab(d[2*p],   al0,al1,al2,al3, bh[0],bh[1]);
            mmab(d[2*p],   ah0,ah1,ah2,ah3, bl[0],bl[1]);
            mmab(d[2*p+1], ah0,ah1,ah2,ah3, bh[2],bh[3]);
            mmab(d[2*p+1], al0,al1,al2,al3, bh[2],bh[3]);
            mmab(d[2*p+1], ah0,ah1,ah2,ah3, bl[2],bl[3]);
        }
    }
}

// stage row-major fp32 [rows][64] -> packed along k
__device__ __forceinline__ void stage_k(u32* Dh, u32* Dl, const float* __restrict__ src,
                                        int rows, int tid, int nthr, float scale) {
    for (int f = tid; f < rows*16; f += nthr) {
        int r = f >> 4, q = f & 15;
        float4 v = *(const float4*)(src + r*64 + 4*q);
        v.x *= scale; v.y *= scale; v.z *= scale; v.w *= scale;
        u32 h0, l0, h1, l1;
        bfsplit(v.x, v.y, h0, l0);
        bfsplit(v.z, v.w, h1, l1);
        *(u64t*)(Dh + r*PW + 2*q) = (u64t)h0 | ((u64t)h1 << 32);
        *(u64t*)(Dl + r*PW + 2*q) = (u64t)l0 | ((u64t)l1 << 32);
    }
}

// stage V [64 s][64 d] -> packed along s
__device__ __forceinline__ void stage_v(u32* Dh, u32* Dl, const float* __restrict__ src,
                                        int tid, int nthr) {
    for (int f = tid; f < 512; f += nthr) {
        int c = f & 63, grp = f >> 6;
        int s0 = grp*8;
        float v[8];
#pragma unroll
        for (int j = 0; j < 8; j++) v[j] = src[(s0+j)*64 + c];
        u32 h[4], l[4];
#pragma unroll
        for (int i = 0; i < 4; i++) bfsplit(v[2*i], v[2*i+1], h[i], l[i]);
        *(uint4*)(Dh + c*PW + 4*grp) = make_uint4(h[0], h[1], h[2], h[3]);
        *(uint4*)(Dl + c*PW + 4*grp) = make_uint4(l[0], l[1], l[2], l[3]);
    }
}

// ---------------- plain FFMA2 64x64 matmul core ----------------
__device__ __forceinline__ void mm64_core(const float* __restrict__ A,
                                          const float* __restrict__ B,
                                          int rq, int cq, u64t acc[4][2]) {
#pragma unroll
    for (int k = 0; k < 64; k++) {
        u64t b0 = *(const u64t*)(B + k*PB + 2*cq);
        u64t b1 = *(const u64t*)(B + k*PB + 2*cq + 32);
#pragma unroll
        for (int r = 0; r < 4; r++) {
            float a = A[(rq + 16*r)*PB + k];
            u64t a2 = pk2(a, a);
            acc[r][0] = ffma2(a2, b0, acc[r][0]);
            acc[r][1] = ffma2(a2, b1, acc[r][1]);
        }
    }
}
__device__ __noinline__ void mm64_smem(const float* __restrict__ A,
                                       const float* __restrict__ B,
                                       float* __restrict__ C, int tid) {
    int cq = tid & 15, rq = tid >> 4;
    u64t acc[4][2] = {};
    mm64_core(A, B, rq, cq, acc);
#pragma unroll
    for (int r = 0; r < 4; r++) {
        *(u64t*)(C + (rq+16*r)*PB + 2*cq)      = acc[r][0];
        *(u64t*)(C + (rq+16*r)*PB + 2*cq + 32) = acc[r][1];
    }
}
__device__ __forceinline__ void tr_write(float* Ct, int rq, int cq, float aI, float bS,
                                         const u64t acc[4][2]) {
    int j0 = 2*cq, j2 = 2*cq + 32;
#pragma unroll
    for (int r = 0; r < 4; r++) {
        int row = rq + 16*r;
        float v0, v1, v2, v3;
        asm("mov.b64 {%0, %1}, %2;" : "=f"(v0), "=f"(v1) : "l"(acc[r][0]));
        asm("mov.b64 {%0, %1}, %2;" : "=f"(v2), "=f"(v3) : "l"(acc[r][1]));
        float t0 = (row == j0   ? aI : 0.f) - bS*v0;
        float t1 = (row == j0+1 ? aI : 0.f) - bS*v1;
        float t2 = (row == j2   ? aI : 0.f) - bS*v2;
        float t3 = (row == j2+1 ? aI : 0.f) - bS*v3;
        *(u64t*)(Ct + row*PB + j0) = pk2(t0, t1);
        *(u64t*)(Ct + row*PB + j2) = pk2(t2, t3);
    }
}
__device__ __forceinline__ void raw_write(float* C, int rq, int cq, const u64t acc[4][2]) {
#pragma unroll
    for (int r = 0; r < 4; r++) {
        int row = rq + 16*r;
        *(u64t*)(C + row*PB + 2*cq)      = acc[r][0];
        *(u64t*)(C + row*PB + 2*cq + 32) = acc[r][1];
    }
}

// ---------------- pooling ----------------
__global__ void __launch_bounds__(256) pool_kernel(const float* __restrict__ Q,
                                                   const float* __restrict__ K) {
    int bh = blockIdx.x >> 6, lm = blockIdx.x & 63;
    int d = threadIdx.x & 63, rg = threadIdx.x >> 6;
    const float* qb = Q + ((size_t)bh*SQ + lm*64)*64 + d;
    const float* kb = K + ((size_t)bh*SQ + lm*64)*64 + d;
    float sq = 0.f, sk = 0.f;
    for (int r = rg; r < 64; r += 4) { sq += qb[(size_t)r*64]; sk += kb[(size_t)r*64]; }
    __shared__ float shq[256], shk[256];
    shq[threadIdx.x] = sq; shk[threadIdx.x] = sk;
    __syncthreads();
    if (rg == 0) {
        float q = (shq[d] + shq[64+d] + shq[128+d] + shq[192+d]) * (1.0f/512.0f);
        float k = (shk[d] + shk[64+d] + shk[128+d] + shk[192+d]) * (1.0f/64.0f);
        g_Qlm [bh*4096 + lm*64 + d] = q;
        g_Klm [bh*4096 + lm*64 + d] = k;
        g_KlmT[bh*4096 + d*64 + lm] = k;
    }
}

// ---------------- Newton-Schulz body: 4 buffers, exact fp32 trajectory ----------------
__device__ void newton_body(float* sm, int bh) {
    float* A = sm;
    float* X = sm + 1*64*PB;
    float* Y = sm + 2*64*PB;
    float* Z = sm + 3*64*PB;
    __shared__ float nsred[256], nsrow[64], nscol[64], nscale[1];
    int tid = threadIdx.x;
    int cq = tid & 15, rq = tid >> 4;

    for (int idx = tid; idx < 4096; idx += 256) {
        int i = idx >> 6, k = idx & 63;
        Y[i*PB + k] = g_Qlm[bh*4096 + idx];
        Z[i*PB + k] = g_KlmT[bh*4096 + idx];
    }
    __syncthreads();
    mm64_smem(Y, Z, A, tid);
    __syncthreads();
    {
        int q = tid & 3, r = tid >> 2;
        float* Lr = A + r*PB + q*16;
        float mt = Lr[0];
#pragma unroll
        for (int c = 1; c < 16; c++) mt = fmaxf(mt, Lr[c]);
        nsred[tid] = mt; __syncthreads();
        float m = fmaxf(fmaxf(nsred[r*4], nsred[r*4+1]), fmaxf(nsred[r*4+2], nsred[r*4+3]));
        float ps = 0.f;
#pragma unroll
        for (int c = 0; c < 16; c++) { float e = __expf(Lr[c] - m); Lr[c] = e; ps += e; }
        __syncthreads();
        nsred[tid] = ps; __syncthreads();
        float inv = 1.0f / (nsred[r*4] + nsred[r*4+1] + nsred[r*4+2] + nsred[r*4+3]);
#pragma unroll
        for (int c = 0; c < 16; c++) Lr[c] *= inv;
    }
    __syncthreads();
    if (tid < 64)       { float s = 0.f; for (int j = 0; j < 64; j++) s += A[tid*PB + j]; nsrow[tid] = s; }
    else if (tid < 128) { int c = tid - 64; float s = 0.f; for (int i = 0; i < 64; i++) s += A[i*PB + c]; nscol[c] = s; }
    __syncthreads();
    if (tid == 0) {
        float mr = nsrow[0], mc = nscol[0];
        for (int i = 1; i < 64; i++) { mr = fmaxf(mr, nsrow[i]); mc = fmaxf(mc, nscol[i]); }
        nscale[0] = 1.0f / (mr * mc);
    }
    __syncthreads();
    float sc = nscale[0];
    for (int idx = tid; idx < 4096; idx += 256) {
        int i = idx >> 6, j = idx & 63;
        X[j*PB + i] = A[i*PB + j] * sc;
    }
    __syncthreads();

    float *Vb = X, *F1 = Y, *F2 = Z;
#pragma unroll 1
    for (int it = 0; it < 6; it++) {
        {
            u64t acc[4][2] = {};
            mm64_core(A, Vb, rq, cq, acc);
            raw_write(F1, rq, cq, acc);
            tr_write(F2, rq, cq, 7.0f, 1.0f, acc);
        }
        __syncthreads();
        {
            u64t acc[4][2] = {};
            mm64_core(F1, F2, rq, cq, acc);
            __syncthreads();
            tr_write(F2, rq, cq, 15.0f, 1.0f, acc);
        }
        __syncthreads();
        {
            u64t acc[4][2] = {};
            mm64_core(F1, F2, rq, cq, acc);
            __syncthreads();
            tr_write(F1, rq, cq, 3.25f, 0.25f, acc);
        }
        __syncthreads();
        {
            u64t acc[4][2] = {};
            mm64_core(Vb, F1, rq, cq, acc);
            raw_write(F2, rq, cq, acc);
        }
        __syncthreads();
        float* nv = F2; F2 = F1; F1 = Vb; Vb = nv;
    }
    for (int idx = tid; idx < 4096; idx += 256) {
        int i = idx >> 6, j = idx & 63;
        g_Inv[bh*4096 + idx] = Vb[i*PB + j];
    }
}

// ---------------- kc body: 8 warps = (lm-quarter x s-half); P stays in regs ----------------
__device__ void kc_body(const float* __restrict__ K, const float* __restrict__ V,
                        u32* sm, int sp, int bh) {
    u32* Qlh = sm;
    u32* Qll = sm + 64*PW;
    u32* Kh  = sm + 2*64*PW;
    u32* Kl  = sm + 3*64*PW;
    u32* Vh  = sm + 4*64*PW;
    u32* Vl  = sm + 5*64*PW;
    int tid = threadIdx.x, lane = tid & 31, wid = tid >> 5;
    int g = lane >> 2, t = lane & 3;
    int wd = wid & 3, half = wid >> 2;
    int base = wd*16, nb = half*32, co = half*16;

    stage_k(Qlh, Qll, g_Qlm + bh*4096, 64, tid, 256, 1.0f);   // already *0.125

    float acc[8][4] = {};
    float rs0 = 0.f, rs1 = 0.f;

#pragma unroll 1
    for (int it = 0; it < 4; it++) {
        int s0 = sp*256 + it*64;
        stage_k(Kh, Kl, K + ((size_t)bh*SQ + s0)*64, 64, tid, 256, 1.0f);
        stage_v(Vh, Vl, V + ((size_t)bh*SQ + s0)*64, tid, 256);
        __syncthreads();

        float c[4][4] = {};
        wg16x32(Qlh, Qll, base, Kh, Kl, nb, lane, c);   // logits[16 lm][32 s-half]

#pragma unroll
        for (int n = 0; n < 4; n++) {
            c[n][0] = __expf(c[n][0]); c[n][1] = __expf(c[n][1]);
            c[n][2] = __expf(c[n][2]); c[n][3] = __expf(c[n][3]);
            rs0 += c[n][0] + c[n][1];
            rs1 += c[n][2] + c[n][3];
        }
        wg_regA_k32(c, Vh, Vl, co, lane, acc);          // acc += P @ V(s-half)
        __syncthreads();                                // V/K reads done before restage
    }

    rs0 += __shfl_xor_sync(0xffffffffu, rs0, 1);
    rs0 += __shfl_xor_sync(0xffffffffu, rs0, 2);
    rs1 += __shfl_xor_sync(0xffffffffu, rs1, 1);
    rs1 += __shfl_xor_sync(0xffffffffu, rs1, 2);

    int osp = sp*2 + half;
    size_t pb = ((size_t)osp*BHN + bh)*4096;
    int r0 = base + g;
#pragma unroll
    for (int nt = 0; nt < 8; nt++) {
        int col = 8*nt + 2*t;
        *(float2*)(g_pacc + pb + r0*64 + col)     = make_float2(acc[nt][0], acc[nt][1]);
        *(float2*)(g_pacc + pb + (r0+8)*64 + col) = make_float2(acc[nt][2], acc[nt][3]);
    }
    if (t == 0) {
        float* ps = g_psum + (osp*BHN+bh)*64;
        ps[r0]     = rs0;
        ps[r0 + 8] = rs1;
    }
}

__global__ void __launch_bounds__(256, 3) mega_kernel(const float* __restrict__ K,
                                                      const float* __restrict__ V) {
    extern __shared__ __align__(16) u32 smg[];
    if (blockIdx.x < 64) newton_body((float*)smg, blockIdx.x);
    else { int id = blockIdx.x - 64; kc_body(K, V, smg, id & (NSP-1), id >> 4); }
}

// ---------------- reduce splits -> F, W = Inv@F, store W^T ----------------
__global__ void __launch_bounds__(256) reduce_winv_kernel() {
    extern __shared__ __align__(16) float smr[];
    float* Fs = smr;
    float* Iv = smr + 64*PB;
    int bh = blockIdx.x, tid = threadIdx.x;

    for (int idx = tid; idx < 4096; idx += 256)
        Iv[(idx>>6)*PB + (idx&63)] = g_Inv[bh*4096 + idx];

    int d = tid & 63, ig = tid >> 6;
    for (int i = ig; i < 64; i += 4) {
        float tot = 0.f;
#pragma unroll
        for (int s = 0; s < NS2; s++) tot += g_psum[(s*BHN+bh)*64 + i];
        float v = 0.f;
#pragma unroll
        for (int s = 0; s < NS2; s++)
            v += g_pacc[((size_t)s*BHN+bh)*4096 + i*64 + d];
        Fs[i*PB + d] = v / tot;
    }
    __syncthreads();
    int cq = tid & 15, rq = tid >> 4;
    u64t acc[4][2] = {};
    mm64_core(Iv, Fs, rq, cq, acc);
    float* wt = g_WT + (size_t)bh*4096;
#pragma unroll
    for (int rr = 0; rr < 4; rr++) {
        int row = rq + 16*rr;
        float v0, v1, v2, v3;
        asm("mov.b64 {%0, %1}, %2;" : "=f"(v0), "=f"(v1) : "l"(acc[rr][0]));
        asm("mov.b64 {%0, %1}, %2;" : "=f"(v2), "=f"(v3) : "l"(acc[rr][1]));
        wt[(2*cq)*64    + row] = v0;
        wt[(2*cq+1)*64  + row] = v1;
        wt[(2*cq+32)*64 + row] = v2;
        wt[(2*cq+33)*64 + row] = v3;
    }
}

// ---------------- kd: 8 warps, M=16/warp, 2 tiles/CTA, P stays in regs ----------------
__global__ void __launch_bounds__(256, 3) kd_bf(const float* __restrict__ Q,
                                                float* __restrict__ X) {
    extern __shared__ __align__(16) u32 smk[];
    u32* Qh = smk;
    u32* Ql = Qh + 128*PW;
    u32* Kh = Ql + 128*PW;
    u32* Kl = Kh + 64*PW;
    u32* Wh = Kl + 64*PW;
    u32* Wl = Wh + 64*PW;
    int tid = threadIdx.x, lane = tid & 31, wid = tid >> 5;
    int g = lane >> 2, t = lane & 3;
    int bh = blockIdx.y;

    stage_k(Kh, Kl, g_Klm + (size_t)bh*4096, 64, tid, 256, 1.0f);
    stage_k(Wh, Wl, g_WT  + (size_t)bh*4096, 64, tid, 256, 1.0f);

    int base = wid*16;
    int r0 = base + g;

#pragma unroll 1
    for (int t2 = 0; t2 < 2; t2++) {
        int tile = blockIdx.x*2 + t2;
        if (t2) __syncthreads();    // all MMA1 Q reads done before restage
        stage_k(Qh, Ql, Q + ((size_t)bh*SQ + tile*128)*64, 128, tid, 256, 0.125f);
        __syncthreads();

        float c[8][4];
#pragma unroll
        for (int n = 0; n < 8; n++) { c[n][0]=0.f; c[n][1]=0.f; c[n][2]=0.f; c[n][3]=0.f; }
        wgemm16(Qh, Ql, base, Kh, Kl, lane, c);   // logits [tok][lm]

        float rs0 = 0.f, rs1 = 0.f;
#pragma unroll
        for (int n = 0; n < 8; n++) {
            c[n][0] = __expf(c[n][0]); c[n][1] = __expf(c[n][1]);
            c[n][2] = __expf(c[n][2]); c[n][3] = __expf(c[n][3]);
            rs0 += c[n][0] + c[n][1];
            rs1 += c[n][2] + c[n][3];
        }
        rs0 += __shfl_xor_sync(0xffffffffu, rs0, 1);
        rs0 += __shfl_xor_sync(0xffffffffu, rs0, 2);
        rs1 += __shfl_xor_sync(0xffffffffu, rs1, 1);
        rs1 += __shfl_xor_sync(0xffffffffu, rs1, 2);
        float rinv0 = 1.0f / rs0, rinv1 = 1.0f / rs1;

        float d[8][4];
#pragma unroll
        for (int n = 0; n < 8; n++) { d[n][0]=0.f; d[n][1]=0.f; d[n][2]=0.f; d[n][3]=0.f; }
        wgemm16_regA(c, Wh, Wl, lane, d);         // X~ = P @ W (P from regs)

        float* x0 = X + ((size_t)bh*SQ + tile*128)*64;
#pragma unroll
        for (int nt = 0; nt < 8; nt++) {
            int col = 8*nt + 2*t;
            *(float2*)(x0 + r0*64 + col)     = make_float2(d[nt][0]*rinv0, d[nt][1]*rinv0);
            *(float2*)(x0 + (r0+8)*64 + col) = make_float2(d[nt][2]*rinv1, d[nt][3]*rinv1);
        }
    }
}

// ---------------- launcher ----------------
extern "C" void kernel_launch(void* const* d_in, const int* in_sizes, int n_in,
                              void* d_out, int out_size) {
    (void)in_sizes; (void)n_in; (void)out_size;
    const float* Q = (const float*)d_in[0];
    const float* K = (const float*)d_in[1];
    const float* V = (const float*)d_in[2];
    float* X = (float*)d_out;

    const int SMEM_MEGA = 4*64*PB*4;    // 69632 (newton); kc uses 55296 -> 3 CTAs/SM
    const int SMEM_RW   = 2*64*PB*4;    // 34816
    const int SMEM_KD   = 512*PW*4;     // 73728 -> 3 CTAs/SM
    cudaFuncSetAttribute(mega_kernel,        cudaFuncAttributeMaxDynamicSharedMemorySize, SMEM_MEGA);
    cudaFuncSetAttribute(reduce_winv_kernel, cudaFuncAttributeMaxDynamicSharedMemorySize, SMEM_RW);
    cudaFuncSetAttribute(kd_bf,              cudaFuncAttributeMaxDynamicSharedMemorySize, SMEM_KD);

    pool_kernel<<<BHN*64, 256>>>(Q, K);
    mega_kernel<<<64 + NSP*BHN, 256, SMEM_MEGA>>>(K, V);
    reduce_winv_kernel<<<BHN, 256, SMEM_RW>>>();
    kd_bf<<<dim3(16, BHN), 256, SMEM_KD>>>(Q, X);
}

// round 14
// speedup vs baseline: 1.1041x; 1.1041x over previous
#include <cuda_runtime.h>
#include <cuda_bf16.h>
#include <cstdint>

#define SQ   4096
#define BHN  64
#define PB   68     // fp32 smem pitch (floats)
#define PW   36     // packed bf16x2 word pitch
#define NS2  16     // softmax splits

typedef unsigned long long u64t;
typedef unsigned int u32;

// ---------------- scratch ----------------
__device__ float g_Qlm [BHN*64*64];
__device__ float g_KlmT[BHN*64*64];
__device__ float g_Klm [BHN*64*64];
__device__ float g_Inv [BHN*64*64];
__device__ float g_WT  [BHN*64*64];   // (inv@F)^T : [d][m]
__device__ float g_pacc[(size_t)NS2*BHN*64*64];
__device__ float g_psum[NS2*BHN*64];

// ---------------- scalar helpers ----------------
__device__ __forceinline__ u64t pk2(float lo, float hi) {
    u64t r; asm("mov.b64 %0, {%1, %2};" : "=l"(r) : "f"(lo), "f"(hi)); return r;
}
__device__ __forceinline__ u64t ffma2(u64t a, u64t b, u64t c) {
    u64t d; asm("fma.rn.f32x2 %0, %1, %2, %3;" : "=l"(d) : "l"(a), "l"(b), "l"(c)); return d;
}
__device__ __forceinline__ u32 bfpack(float x, float y) {
    __nv_bfloat162 h = __floats2bfloat162_rn(x, y);
    return *reinterpret_cast<u32*>(&h);
}
__device__ __forceinline__ void bfsplit(float x, float y, u32& hw, u32& lw) {
    __nv_bfloat162 h = __floats2bfloat162_rn(x, y);
    float hx = __bfloat162float(h.x), hy = __bfloat162float(h.y);
    hw = *reinterpret_cast<u32*>(&h);
    lw = bfpack(x - hx, y - hy);
}
__device__ __forceinline__ void mmab(float c[4], u32 a0, u32 a1, u32 a2, u32 a3,
                                     u32 b0, u32 b1) {
    asm volatile("mma.sync.aligned.m16n8k16.row.col.f32.bf16.bf16.f32 "
        "{%0,%1,%2,%3}, {%4,%5,%6,%7}, {%8,%9}, {%0,%1,%2,%3};"
        : "+f"(c[0]), "+f"(c[1]), "+f"(c[2]), "+f"(c[3])
        : "r"(a0), "r"(a1), "r"(a2), "r"(a3), "r"(b0), "r"(b1));
}
__device__ __forceinline__ u32 sptr(const void* p) {
    u32 a;
    asm("{ .reg .u64 t; cvta.to.shared.u64 t, %1; cvt.u32.u64 %0, t; }" : "=r"(a) : "l"(p));
    return a;
}
__device__ __forceinline__ void ldsm4(u32* r, u32 addr) {
    asm volatile("ldmatrix.sync.aligned.m8n8.x4.shared.b16 {%0,%1,%2,%3}, [%4];"
        : "=r"(r[0]), "=r"(r[1]), "=r"(r[2]), "=r"(r[3]) : "r"(addr));
}

// warp gemm: C[16x64] += A[16 rows, k=64] @ B[64 n, k=64]  (kd MMA1)
__device__ __forceinline__ void wgemm16(const u32* __restrict__ Ah, const u32* __restrict__ Al,
                                        int base,
                                        const u32* __restrict__ Bh, const u32* __restrict__ Bl,
                                        int lane, float c[8][4]) {
    int mi = lane >> 3, lr = lane & 7;
    u32 aH = sptr(Ah + (base + (mi & 1)*8 + lr)*PW + (mi >> 1)*4);
    u32 aL = sptr(Al + (base + (mi & 1)*8 + lr)*PW + (mi >> 1)*4);
    u32 bH = sptr(Bh + ((mi >> 1)*8 + lr)*PW + (mi & 1)*4);
    u32 bL = sptr(Bl + ((mi >> 1)*8 + lr)*PW + (mi & 1)*4);
#pragma unroll
    for (int kt = 0; kt < 4; kt++) {
        u32 ah[4], al[4];
        ldsm4(ah, aH + kt*32);
        ldsm4(al, aL + kt*32);
#pragma unroll
        for (int p = 0; p < 4; p++) {
            u32 bh[4], bl[4];
            ldsm4(bh, bH + p*(16*PW*4) + kt*32);
            ldsm4(bl, bL + p*(16*PW*4) + kt*32);
            mmab(c[2*p],   ah[0],ah[1],ah[2],ah[3], bh[0],bh[1]);
            mmab(c[2*p],   al[0],al[1],al[2],al[3], bh[0],bh[1]);
            mmab(c[2*p],   ah[0],ah[1],ah[2],ah[3], bl[0],bl[1]);
            mmab(c[2*p+1], ah[0],ah[1],ah[2],ah[3], bh[2],bh[3]);
            mmab(c[2*p+1], al[0],al[1],al[2],al[3], bh[2],bh[3]);
            mmab(c[2*p+1], ah[0],ah[1],ah[2],ah[3], bl[2],bl[3]);
        }
    }
}

// MMA2 from register P (kd): d[16x64] += P(c regs, k=64) @ B[64 n, k=64]
__device__ __forceinline__ void wgemm16_regA(const float c[8][4],
                                             const u32* __restrict__ Bh,
                                             const u32* __restrict__ Bl,
                                             int lane, float d[8][4]) {
    int mi = lane >> 3, lr = lane & 7;
    u32 bH = sptr(Bh + ((mi >> 1)*8 + lr)*PW + (mi & 1)*4);
    u32 bL = sptr(Bl + ((mi >> 1)*8 + lr)*PW + (mi & 1)*4);
#pragma unroll
    for (int kt = 0; kt < 4; kt++) {
        u32 ah0, al0, ah1, al1, ah2, al2, ah3, al3;
        bfsplit(c[2*kt][0],   c[2*kt][1],   ah0, al0);
        bfsplit(c[2*kt][2],   c[2*kt][3],   ah1, al1);
        bfsplit(c[2*kt+1][0], c[2*kt+1][1], ah2, al2);
        bfsplit(c[2*kt+1][2], c[2*kt+1][3], ah3, al3);
#pragma unroll
        for (int p = 0; p < 4; p++) {
            u32 bh[4], bl[4];
            ldsm4(bh, bH + p*(16*PW*4) + kt*32);
            ldsm4(bl, bL + p*(16*PW*4) + kt*32);
            mmab(d[2*p],   ah0,ah1,ah2,ah3, bh[0],bh[1]);
            mmab(d[2*p],   al0,al1,al2,al3, bh[0],bh[1]);
            mmab(d[2*p],   ah0,ah1,ah2,ah3, bl[0],bl[1]);
            mmab(d[2*p+1], ah0,ah1,ah2,ah3, bh[2],bh[3]);
            mmab(d[2*p+1], al0,al1,al2,al3, bh[2],bh[3]);
            mmab(d[2*p+1], ah0,ah1,ah2,ah3, bl[2],bl[3]);
        }
    }
}

// warp gemm: C[16x32] += A[16 rows, k=64] @ B[n = nbase..nbase+31, k=64]  (kc)
__device__ __forceinline__ void wg16x32(const u32* __restrict__ Ah, const u32* __restrict__ Al,
                                        int base,
                                        const u32* __restrict__ Bh, const u32* __restrict__ Bl,
                                        int nbase, int lane, float c[4][4]) {
    int mi = lane >> 3, lr = lane & 7;
    u32 aH = sptr(Ah + (base + (mi & 1)*8 + lr)*PW + (mi >> 1)*4);
    u32 aL = sptr(Al + (base + (mi & 1)*8 + lr)*PW + (mi >> 1)*4);
    u32 bH = sptr(Bh + (nbase + (mi >> 1)*8 + lr)*PW + (mi & 1)*4);
    u32 bL = sptr(Bl + (nbase + (mi >> 1)*8 + lr)*PW + (mi & 1)*4);
#pragma unroll
    for (int kt = 0; kt < 4; kt++) {
        u32 ah[4], al[4];
        ldsm4(ah, aH + kt*32);
        ldsm4(al, aL + kt*32);
#pragma unroll
        for (int p = 0; p < 2; p++) {
            u32 bh[4], bl[4];
            ldsm4(bh, bH + p*(16*PW*4) + kt*32);
            ldsm4(bl, bL + p*(16*PW*4) + kt*32);
            mmab(c[2*p],   ah[0],ah[1],ah[2],ah[3], bh[0],bh[1]);
            mmab(c[2*p],   al[0],al[1],al[2],al[3], bh[0],bh[1]);
            mmab(c[2*p],   ah[0],ah[1],ah[2],ah[3], bl[0],bl[1]);
            mmab(c[2*p+1], ah[0],ah[1],ah[2],ah[3], bh[2],bh[3]);
            mmab(c[2*p+1], al[0],al[1],al[2],al[3], bh[2],bh[3]);
            mmab(c[2*p+1], ah[0],ah[1],ah[2],ah[3], bl[2],bl[3]);
        }
    }
}

// write P (16 rows, 32-col half at word offset co) into packed layout (kc)
__device__ __forceinline__ void write_P32(u32* Ph, u32* Pl, int base, int co, int g, int t,
                                          const float c[4][4]) {
    int r0 = base + g;
#pragma unroll
    for (int nt = 0; nt < 4; nt++) {
        u32 hw, lw;
        bfsplit(c[nt][0], c[nt][1], hw, lw);
        Ph[r0*PW + co + 4*nt + t] = hw;  Pl[r0*PW + co + 4*nt + t] = lw;
        bfsplit(c[nt][2], c[nt][3], hw, lw);
        Ph[(r0+8)*PW + co + 4*nt + t] = hw;  Pl[(r0+8)*PW + co + 4*nt + t] = lw;
    }
}

// stage row-major fp32 [rows][64] -> packed along k
__device__ __forceinline__ void stage_k(u32* Dh, u32* Dl, const float* __restrict__ src,
                                        int rows, int tid, int nthr, float scale) {
    for (int f = tid; f < rows*16; f += nthr) {
        int r = f >> 4, q = f & 15;
        float4 v = *(const float4*)(src + r*64 + 4*q);
        v.x *= scale; v.y *= scale; v.z *= scale; v.w *= scale;
        u32 h0, l0, h1, l1;
        bfsplit(v.x, v.y, h0, l0);
        bfsplit(v.z, v.w, h1, l1);
        *(u64t*)(Dh + r*PW + 2*q) = (u64t)h0 | ((u64t)h1 << 32);
        *(u64t*)(Dl + r*PW + 2*q) = (u64t)l0 | ((u64t)l1 << 32);
    }
}

// stage V [64 s][64 d] -> packed along s
__device__ __forceinline__ void stage_v(u32* Dh, u32* Dl, const float* __restrict__ src,
                                        int tid, int nthr) {
    for (int f = tid; f < 512; f += nthr) {
        int c = f & 63, grp = f >> 6;
        int s0 = grp*8;
        float v[8];
#pragma unroll
        for (int j = 0; j < 8; j++) v[j] = src[(s0+j)*64 + c];
        u32 h[4], l[4];
#pragma unroll
        for (int i = 0; i < 4; i++) bfsplit(v[2*i], v[2*i+1], h[i], l[i]);
        *(uint4*)(Dh + c*PW + 4*grp) = make_uint4(h[0], h[1], h[2], h[3]);
        *(uint4*)(Dl + c*PW + 4*grp) = make_uint4(l[0], l[1], l[2], l[3]);
    }
}

// ---------------- plain FFMA2 64x64 matmul core ----------------
__device__ __forceinline__ void mm64_core(const float* __restrict__ A,
                                          const float* __restrict__ B,
                                          int rq, int cq, u64t acc[4][2]) {
#pragma unroll
    for (int k = 0; k < 64; k++) {
        u64t b0 = *(const u64t*)(B + k*PB + 2*cq);
        u64t b1 = *(const u64t*)(B + k*PB + 2*cq + 32);
#pragma unroll
        for (int r = 0; r < 4; r++) {
            float a = A[(rq + 16*r)*PB + k];
            u64t a2 = pk2(a, a);
            acc[r][0] = ffma2(a2, b0, acc[r][0]);
            acc[r][1] = ffma2(a2, b1, acc[r][1]);
        }
    }
}
__device__ __noinline__ void mm64_smem(const float* __restrict__ A,
                                       const float* __restrict__ B,
                                       float* __restrict__ C, int tid) {
    int cq = tid & 15, rq = tid >> 4;
    u64t acc[4][2] = {};
    mm64_core(A, B, rq, cq, acc);
#pragma unroll
    for (int r = 0; r < 4; r++) {
        *(u64t*)(C + (rq+16*r)*PB + 2*cq)      = acc[r][0];
        *(u64t*)(C + (rq+16*r)*PB + 2*cq + 32) = acc[r][1];
    }
}
__device__ __forceinline__ void tr_write(float* Ct, int rq, int cq, float aI, float bS,
                                         const u64t acc[4][2]) {
    int j0 = 2*cq, j2 = 2*cq + 32;
#pragma unroll
    for (int r = 0; r < 4; r++) {
        int row = rq + 16*r;
        float v0, v1, v2, v3;
        asm("mov.b64 {%0, %1}, %2;" : "=f"(v0), "=f"(v1) : "l"(acc[r][0]));
        asm("mov.b64 {%0, %1}, %2;" : "=f"(v2), "=f"(v3) : "l"(acc[r][1]));
        float t0 = (row == j0   ? aI : 0.f) - bS*v0;
        float t1 = (row == j0+1 ? aI : 0.f) - bS*v1;
        float t2 = (row == j2   ? aI : 0.f) - bS*v2;
        float t3 = (row == j2+1 ? aI : 0.f) - bS*v3;
        *(u64t*)(Ct + row*PB + j0) = pk2(t0, t1);
        *(u64t*)(Ct + row*PB + j2) = pk2(t2, t3);
    }
}
__device__ __forceinline__ void raw_write(float* C, int rq, int cq, const u64t acc[4][2]) {
#pragma unroll
    for (int r = 0; r < 4; r++) {
        int row = rq + 16*r;
        *(u64t*)(C + row*PB + 2*cq)      = acc[r][0];
        *(u64t*)(C + row*PB + 2*cq + 32) = acc[r][1];
    }
}

// ---------------- pooling ----------------
__global__ void __launch_bounds__(256) pool_kernel(const float* __restrict__ Q,
                                                   const float* __restrict__ K) {
    int bh = blockIdx.x >> 6, lm = blockIdx.x & 63;
    int d = threadIdx.x & 63, rg = threadIdx.x >> 6;
    const float* qb = Q + ((size_t)bh*SQ + lm*64)*64 + d;
    const float* kb = K + ((size_t)bh*SQ + lm*64)*64 + d;
    float sq = 0.f, sk = 0.f;
    for (int r = rg; r < 64; r += 4) { sq += qb[(size_t)r*64]; sk += kb[(size_t)r*64]; }
    __shared__ float shq[256], shk[256];
    shq[threadIdx.x] = sq; shk[threadIdx.x] = sk;
    __syncthreads();
    if (rg == 0) {
        float q = (shq[d] + shq[64+d] + shq[128+d] + shq[192+d]) * (1.0f/512.0f);
        float k = (shk[d] + shk[64+d] + shk[128+d] + shk[192+d]) * (1.0f/64.0f);
        g_Qlm [bh*4096 + lm*64 + d] = q;
        g_Klm [bh*4096 + lm*64 + d] = k;
        g_KlmT[bh*4096 + d*64 + lm] = k;
    }
}

// ---------------- Newton-Schulz body: 4 buffers, exact fp32 trajectory ----------------
__device__ void newton_body(float* sm, int bh) {
    float* A = sm;
    float* X = sm + 1*64*PB;
    float* Y = sm + 2*64*PB;
    float* Z = sm + 3*64*PB;
    __shared__ float nsred[256], nsrow[64], nscol[64], nscale[1];
    int tid = threadIdx.x;
    int cq = tid & 15, rq = tid >> 4;

    for (int idx = tid; idx < 4096; idx += 256) {
        int i = idx >> 6, k = idx & 63;
        Y[i*PB + k] = g_Qlm[bh*4096 + idx];
        Z[i*PB + k] = g_KlmT[bh*4096 + idx];
    }
    __syncthreads();
    mm64_smem(Y, Z, A, tid);
    __syncthreads();
    {
        int q = tid & 3, r = tid >> 2;
        float* Lr = A + r*PB + q*16;
        float mt = Lr[0];
#pragma unroll
        for (int c = 1; c < 16; c++) mt = fmaxf(mt, Lr[c]);
        nsred[tid] = mt; __syncthreads();
        float m = fmaxf(fmaxf(nsred[r*4], nsred[r*4+1]), fmaxf(nsred[r*4+2], nsred[r*4+3]));
        float ps = 0.f;
#pragma unroll
        for (int c = 0; c < 16; c++) { float e = __expf(Lr[c] - m); Lr[c] = e; ps += e; }
        __syncthreads();
        nsred[tid] = ps; __syncthreads();
        float inv = 1.0f / (nsred[r*4] + nsred[r*4+1] + nsred[r*4+2] + nsred[r*4+3]);
#pragma unroll
        for (int c = 0; c < 16; c++) Lr[c] *= inv;
    }
    __syncthreads();
    if (tid < 64)       { float s = 0.f; for (int j = 0; j < 64; j++) s += A[tid*PB + j]; nsrow[tid] = s; }
    else if (tid < 128) { int c = tid - 64; float s = 0.f; for (int i = 0; i < 64; i++) s += A[i*PB + c]; nscol[c] = s; }
    __syncthreads();
    if (tid == 0) {
        float mr = nsrow[0], mc = nscol[0];
        for (int i = 1; i < 64; i++) { mr = fmaxf(mr, nsrow[i]); mc = fmaxf(mc, nscol[i]); }
        nscale[0] = 1.0f / (mr * mc);
    }
    __syncthreads();
    float sc = nscale[0];
    for (int idx = tid; idx < 4096; idx += 256) {
        int i = idx >> 6, j = idx & 63;
        X[j*PB + i] = A[i*PB + j] * sc;
    }
    __syncthreads();

    float *Vb = X, *F1 = Y, *F2 = Z;
#pragma unroll 1
    for (int it = 0; it < 6; it++) {
        {
            u64t acc[4][2] = {};
            mm64_core(A, Vb, rq, cq, acc);
            raw_write(F1, rq, cq, acc);
            tr_write(F2, rq, cq, 7.0f, 1.0f, acc);
        }
        __syncthreads();
        {
            u64t acc[4][2] = {};
            mm64_core(F1, F2, rq, cq, acc);
            __syncthreads();
            tr_write(F2, rq, cq, 15.0f, 1.0f, acc);
        }
        __syncthreads();
        {
            u64t acc[4][2] = {};
            mm64_core(F1, F2, rq, cq, acc);
            __syncthreads();
            tr_write(F1, rq, cq, 3.25f, 0.25f, acc);
        }
        __syncthreads();
        {
            u64t acc[4][2] = {};
            mm64_core(Vb, F1, rq, cq, acc);
            raw_write(F2, rq, cq, acc);
        }
        __syncthreads();
        float* nv = F2; F2 = F1; F1 = Vb; Vb = nv;
    }
    for (int idx = tid; idx < 4096; idx += 256) {
        int i = idx >> 6, j = idx & 63;
        g_Inv[bh*4096 + idx] = Vb[i*PB + j];
    }
}

// ---------------- kc body: 8 warps share one tile (M x s/d split), smem P ----------------
__device__ void kc_body(const float* __restrict__ K, const float* __restrict__ V,
                        u32* sm, int sp, int bh) {
    u32* Qlh = sm;
    u32* Qll = sm + 64*PW;
    u32* KPh = sm + 2*64*PW;   // K tile, later P
    u32* KPl = sm + 3*64*PW;
    u32* Vh  = sm + 4*64*PW;
    u32* Vl  = sm + 5*64*PW;
    __shared__ float srs[8][16];
    int tid = threadIdx.x, lane = tid & 31, wid = tid >> 5;
    int g = lane >> 2, t = lane & 3;
    int wd = wid & 3, half = wid >> 2;
    int base = wd*16, nb = half*32, co = half*16;

    stage_k(Qlh, Qll, g_Qlm + bh*4096, 64, tid, 256, 1.0f);  // already *0.125

    float acc[4][4] = {};
    float rs0 = 0.f, rs1 = 0.f;
    __syncthreads();

#pragma unroll 1
    for (int it = 0; it < 4; it++) {
        int s0 = sp*256 + it*64;
        stage_k(KPh, KPl, K + ((size_t)bh*SQ + s0)*64, 64, tid, 256, 1.0f);
        stage_v(Vh, Vl, V + ((size_t)bh*SQ + s0)*64, tid, 256);
        __syncthreads();

        float c[4][4] = {};
        wg16x32(Qlh, Qll, base, KPh, KPl, nb, lane, c);   // logits[lm 16][s 32]

#pragma unroll
        for (int n = 0; n < 4; n++) {
            c[n][0] = __expf(c[n][0]); c[n][1] = __expf(c[n][1]);
            c[n][2] = __expf(c[n][2]); c[n][3] = __expf(c[n][3]);
            rs0 += c[n][0] + c[n][1];
            rs1 += c[n][2] + c[n][3];
        }
        __syncthreads();                      // all K reads done
        write_P32(KPh, KPl, base, co, g, t, c);
        __syncthreads();                      // P complete (cross-warp)
        wg16x32(KPh, KPl, base, Vh, Vl, nb, lane, acc);   // acc += P@V (d half)
        __syncthreads();                      // before restage
    }

    rs0 += __shfl_xor_sync(0xffffffffu, rs0, 1);
    rs0 += __shfl_xor_sync(0xffffffffu, rs0, 2);
    rs1 += __shfl_xor_sync(0xffffffffu, rs1, 1);
    rs1 += __shfl_xor_sync(0xffffffffu, rs1, 2);
    if (t == 0) { srs[wid][g] = rs0; srs[wid][g + 8] = rs1; }

    size_t pb = ((size_t)sp*BHN + bh)*4096;
    int r0 = base + g;
#pragma unroll
    for (int nt = 0; nt < 4; nt++) {
        int col = nb + 8*nt + 2*t;
        *(float2*)(g_pacc + pb + r0*64 + col)     = make_float2(acc[nt][0], acc[nt][1]);
        *(float2*)(g_pacc + pb + (r0+8)*64 + col) = make_float2(acc[nt][2], acc[nt][3]);
    }
    __syncthreads();
    if (half == 0 && lane < 16) {
        float tot = srs[wid][lane] + srs[wid + 4][lane];
        g_psum[(sp*BHN + bh)*64 + base + lane] = tot;
    }
}

__global__ void __launch_bounds__(256, 3) mega_kernel(const float* __restrict__ K,
                                                      const float* __restrict__ V) {
    extern __shared__ __align__(16) u32 smg[];
    if (blockIdx.x < 64) newton_body((float*)smg, blockIdx.x);
    else { int id = blockIdx.x - 64; kc_body(K, V, smg, id & (NS2-1), id >> 4); }
}

// ---------------- reduce splits -> F, W = Inv@F, store W^T ----------------
__global__ void __launch_bounds__(256) reduce_winv_kernel() {
    extern __shared__ __align__(16) float smr[];
    float* Fs = smr;
    float* Iv = smr + 64*PB;
    int bh = blockIdx.x, tid = threadIdx.x;

    for (int idx = tid; idx < 4096; idx += 256)
        Iv[(idx>>6)*PB + (idx&63)] = g_Inv[bh*4096 + idx];

    int d = tid & 63, ig = tid >> 6;
    for (int i = ig; i < 64; i += 4) {
        float tot = 0.f;
#pragma unroll
        for (int s = 0; s < NS2; s++) tot += g_psum[(s*BHN+bh)*64 + i];
        float v = 0.f;
#pragma unroll
        for (int s = 0; s < NS2; s++)
            v += g_pacc[((size_t)s*BHN+bh)*4096 + i*64 + d];
        Fs[i*PB + d] = v / tot;
    }
    __syncthreads();
    int cq = tid & 15, rq = tid >> 4;
    u64t acc[4][2] = {};
    mm64_core(Iv, Fs, rq, cq, acc);
    float* wt = g_WT + (size_t)bh*4096;
#pragma unroll
    for (int rr = 0; rr < 4; rr++) {
        int row = rq + 16*rr;
        float v0, v1, v2, v3;
        asm("mov.b64 {%0, %1}, %2;" : "=f"(v0), "=f"(v1) : "l"(acc[rr][0]));
        asm("mov.b64 {%0, %1}, %2;" : "=f"(v2), "=f"(v3) : "l"(acc[rr][1]));
        wt[(2*cq)*64    + row] = v0;
        wt[(2*cq+1)*64  + row] = v1;
        wt[(2*cq+32)*64 + row] = v2;
        wt[(2*cq+33)*64 + row] = v3;
    }
}

// ---------------- kd: 8 warps, M=16/warp, 2 tiles/CTA, P stays in regs ----------------
__global__ void __launch_bounds__(256, 3) kd_bf(const float* __restrict__ Q,
                                                float* __restrict__ X) {
    extern __shared__ __align__(16) u32 smk[];
    u32* Qh = smk;
    u32* Ql = Qh + 128*PW;
    u32* Kh = Ql + 128*PW;
    u32* Kl = Kh + 64*PW;
    u32* Wh = Kl + 64*PW;
    u32* Wl = Wh + 64*PW;
    int tid = threadIdx.x, lane = tid & 31, wid = tid >> 5;
    int g = lane >> 2, t = lane & 3;
    int bh = blockIdx.y;

    stage_k(Kh, Kl, g_Klm + (size_t)bh*4096, 64, tid, 256, 1.0f);
    stage_k(Wh, Wl, g_WT  + (size_t)bh*4096, 64, tid, 256, 1.0f);

    int base = wid*16;
    int r0 = base + g;

#pragma unroll 1
    for (int t2 = 0; t2 < 2; t2++) {
        int tile = blockIdx.x*2 + t2;
        if (t2) __syncthreads();    // all MMA1 Q reads done before restage
        stage_k(Qh, Ql, Q + ((size_t)bh*SQ + tile*128)*64, 128, tid, 256, 0.125f);
        __syncthreads();

        float c[8][4];
#pragma unroll
        for (int n = 0; n < 8; n++) { c[n][0]=0.f; c[n][1]=0.f; c[n][2]=0.f; c[n][3]=0.f; }
        wgemm16(Qh, Ql, base, Kh, Kl, lane, c);   // logits [tok][lm]

        float rs0 = 0.f, rs1 = 0.f;
#pragma unroll
        for (int n = 0; n < 8; n++) {
            c[n][0] = __expf(c[n][0]); c[n][1] = __expf(c[n][1]);
            c[n][2] = __expf(c[n][2]); c[n][3] = __expf(c[n][3]);
            rs0 += c[n][0] + c[n][1];
            rs1 += c[n][2] + c[n][3];
        }
        rs0 += __shfl_xor_sync(0xffffffffu, rs0, 1);
        rs0 += __shfl_xor_sync(0xffffffffu, rs0, 2);
        rs1 += __shfl_xor_sync(0xffffffffu, rs1, 1);
        rs1 += __shfl_xor_sync(0xffffffffu, rs1, 2);
        float rinv0 = 1.0f / rs0, rinv1 = 1.0f / rs1;

        float d[8][4];
#pragma unroll
        for (int n = 0; n < 8; n++) { d[n][0]=0.f; d[n][1]=0.f; d[n][2]=0.f; d[n][3]=0.f; }
        wgemm16_regA(c, Wh, Wl, lane, d);         // X~ = P @ W (P from regs)

        float* x0 = X + ((size_t)bh*SQ + tile*128)*64;
#pragma unroll
        for (int nt = 0; nt < 8; nt++) {
            int col = 8*nt + 2*t;
            *(float2*)(x0 + r0*64 + col)     = make_float2(d[nt][0]*rinv0, d[nt][1]*rinv0);
            *(float2*)(x0 + (r0+8)*64 + col) = make_float2(d[nt][2]*rinv1, d[nt][3]*rinv1);
        }
    }
}

// ---------------- launcher ----------------
extern "C" void kernel_launch(void* const* d_in, const int* in_sizes, int n_in,
                              void* d_out, int out_size) {
    (void)in_sizes; (void)n_in; (void)out_size;
    const float* Q = (const float*)d_in[0];
    const float* K = (const float*)d_in[1];
    const float* V = (const float*)d_in[2];
    float* X = (float*)d_out;

    const int SMEM_MEGA = 4*64*PB*4;    // 69632 (newton); kc uses 55296 -> 3 CTAs/SM
    const int SMEM_RW   = 2*64*PB*4;    // 34816
    const int SMEM_KD   = 512*PW*4;     // 73728 -> 3 CTAs/SM
    cudaFuncSetAttribute(mega_kernel,        cudaFuncAttributeMaxDynamicSharedMemorySize, SMEM_MEGA);
    cudaFuncSetAttribute(reduce_winv_kernel, cudaFuncAttributeMaxDynamicSharedMemorySize, SMEM_RW);
    cudaFuncSetAttribute(kd_bf,              cudaFuncAttributeMaxDynamicSharedMemorySize, SMEM_KD);

    pool_kernel<<<BHN*64, 256>>>(Q, K);
    mega_kernel<<<64 + NS2*BHN, 256, SMEM_MEGA>>>(K, V);
    reduce_winv_kernel<<<BHN, 256, SMEM_RW>>>();
    kd_bf<<<dim3(16, BHN), 256, SMEM_KD>>>(Q, X);
}

// round 15
// speedup vs baseline: 1.2047x; 1.0911x over previous
#include <cuda_runtime.h>
#include <cuda_bf16.h>
#include <cstdint>

#define SQ   4096
#define BHN  64
#define PB   68     // fp32 smem pitch (floats)
#define PW   36     // packed bf16x2 word pitch
#define NS2  16     // softmax splits

typedef unsigned long long u64t;
typedef unsigned int u32;

// ---------------- scratch ----------------
__device__ float g_Qlm [BHN*64*64];
__device__ float g_KlmT[BHN*64*64];
__device__ float g_Klm [BHN*64*64];
__device__ float g_Inv [BHN*64*64];
__device__ float g_WT  [BHN*64*64];   // (inv@F)^T : [d][m]
__device__ float g_pacc[(size_t)NS2*BHN*64*64];
__device__ float g_psum[NS2*BHN*64];

// ---------------- scalar helpers ----------------
__device__ __forceinline__ u64t pk2(float lo, float hi) {
    u64t r; asm("mov.b64 %0, {%1, %2};" : "=l"(r) : "f"(lo), "f"(hi)); return r;
}
__device__ __forceinline__ u64t ffma2(u64t a, u64t b, u64t c) {
    u64t d; asm("fma.rn.f32x2 %0, %1, %2, %3;" : "=l"(d) : "l"(a), "l"(b), "l"(c)); return d;
}
__device__ __forceinline__ u32 bfpack(float x, float y) {
    __nv_bfloat162 h = __floats2bfloat162_rn(x, y);
    return *reinterpret_cast<u32*>(&h);
}
__device__ __forceinline__ void bfsplit(float x, float y, u32& hw, u32& lw) {
    __nv_bfloat162 h = __floats2bfloat162_rn(x, y);
    float hx = __bfloat162float(h.x), hy = __bfloat162float(h.y);
    hw = *reinterpret_cast<u32*>(&h);
    lw = bfpack(x - hx, y - hy);
}
__device__ __forceinline__ void mmab(float c[4], u32 a0, u32 a1, u32 a2, u32 a3,
                                     u32 b0, u32 b1) {
    asm volatile("mma.sync.aligned.m16n8k16.row.col.f32.bf16.bf16.f32 "
        "{%0,%1,%2,%3}, {%4,%5,%6,%7}, {%8,%9}, {%0,%1,%2,%3};"
        : "+f"(c[0]), "+f"(c[1]), "+f"(c[2]), "+f"(c[3])
        : "r"(a0), "r"(a1), "r"(a2), "r"(a3), "r"(b0), "r"(b1));
}
__device__ __forceinline__ u32 sptr(const void* p) {
    u32 a;
    asm("{ .reg .u64 t; cvta.to.shared.u64 t, %1; cvt.u32.u64 %0, t; }" : "=r"(a) : "l"(p));
    return a;
}
__device__ __forceinline__ void ldsm4(u32* r, u32 addr) {
    asm volatile("ldmatrix.sync.aligned.m8n8.x4.shared.b16 {%0,%1,%2,%3}, [%4];"
        : "=r"(r[0]), "=r"(r[1]), "=r"(r[2]), "=r"(r[3]) : "r"(addr));
}

// warp gemm: C[16x64] += A[16 rows, k=64] @ B[64 n, k=64]
__device__ __forceinline__ void wgemm16(const u32* __restrict__ Ah, const u32* __restrict__ Al,
                                        int base,
                                        const u32* __restrict__ Bh, const u32* __restrict__ Bl,
                                        int lane, float c[8][4]) {
    int mi = lane >> 3, lr = lane & 7;
    u32 aH = sptr(Ah + (base + (mi & 1)*8 + lr)*PW + (mi >> 1)*4);
    u32 aL = sptr(Al + (base + (mi & 1)*8 + lr)*PW + (mi >> 1)*4);
    u32 bH = sptr(Bh + ((mi >> 1)*8 + lr)*PW + (mi & 1)*4);
    u32 bL = sptr(Bl + ((mi >> 1)*8 + lr)*PW + (mi & 1)*4);
#pragma unroll
    for (int kt = 0; kt < 4; kt++) {
        u32 ah[4], al[4];
        ldsm4(ah, aH + kt*32);
        ldsm4(al, aL + kt*32);
#pragma unroll
        for (int p = 0; p < 4; p++) {
            u32 bh[4], bl[4];
            ldsm4(bh, bH + p*(16*PW*4) + kt*32);
            ldsm4(bl, bL + p*(16*PW*4) + kt*32);
            mmab(c[2*p],   ah[0],ah[1],ah[2],ah[3], bh[0],bh[1]);
            mmab(c[2*p],   al[0],al[1],al[2],al[3], bh[0],bh[1]);
            mmab(c[2*p],   ah[0],ah[1],ah[2],ah[3], bl[0],bl[1]);
            mmab(c[2*p+1], ah[0],ah[1],ah[2],ah[3], bh[2],bh[3]);
            mmab(c[2*p+1], al[0],al[1],al[2],al[3], bh[2],bh[3]);
            mmab(c[2*p+1], ah[0],ah[1],ah[2],ah[3], bl[2],bl[3]);
        }
    }
}

// MMA2 from register P: d[16x64] += P(c regs, k=64) @ B[64 n, k=64]
__device__ __forceinline__ void wgemm16_regA(const float c[8][4],
                                             const u32* __restrict__ Bh,
                                             const u32* __restrict__ Bl,
                                             int lane, float d[8][4]) {
    int mi = lane >> 3, lr = lane & 7;
    u32 bH = sptr(Bh + ((mi >> 1)*8 + lr)*PW + (mi & 1)*4);
    u32 bL = sptr(Bl + ((mi >> 1)*8 + lr)*PW + (mi & 1)*4);
#pragma unroll
    for (int kt = 0; kt < 4; kt++) {
        u32 ah0, al0, ah1, al1, ah2, al2, ah3, al3;
        bfsplit(c[2*kt][0],   c[2*kt][1],   ah0, al0);
        bfsplit(c[2*kt][2],   c[2*kt][3],   ah1, al1);
        bfsplit(c[2*kt+1][0], c[2*kt+1][1], ah2, al2);
        bfsplit(c[2*kt+1][2], c[2*kt+1][3], ah3, al3);
#pragma unroll
        for (int p = 0; p < 4; p++) {
            u32 bh[4], bl[4];
            ldsm4(bh, bH + p*(16*PW*4) + kt*32);
            ldsm4(bl, bL + p*(16*PW*4) + kt*32);
            mmab(d[2*p],   ah0,ah1,ah2,ah3, bh[0],bh[1]);
            mmab(d[2*p],   al0,al1,al2,al3, bh[0],bh[1]);
            mmab(d[2*p],   ah0,ah1,ah2,ah3, bl[0],bl[1]);
            mmab(d[2*p+1], ah0,ah1,ah2,ah3, bh[2],bh[3]);
            mmab(d[2*p+1], al0,al1,al2,al3, bh[2],bh[3]);
            mmab(d[2*p+1], ah0,ah1,ah2,ah3, bl[2],bl[3]);
        }
    }
}

// stage row-major fp32 [rows][64] -> packed along k
__device__ __forceinline__ void stage_k(u32* Dh, u32* Dl, const float* __restrict__ src,
                                        int rows, int tid, int nthr, float scale) {
    for (int f = tid; f < rows*16; f += nthr) {
        int r = f >> 4, q = f & 15;
        float4 v = *(const float4*)(src + r*64 + 4*q);
        v.x *= scale; v.y *= scale; v.z *= scale; v.w *= scale;
        u32 h0, l0, h1, l1;
        bfsplit(v.x, v.y, h0, l0);
        bfsplit(v.z, v.w, h1, l1);
        *(u64t*)(Dh + r*PW + 2*q) = (u64t)h0 | ((u64t)h1 << 32);
        *(u64t*)(Dl + r*PW + 2*q) = (u64t)l0 | ((u64t)l1 << 32);
    }
}

// stage V [64 s][64 d] -> packed along s
__device__ __forceinline__ void stage_v(u32* Dh, u32* Dl, const float* __restrict__ src,
                                        int tid, int nthr) {
    for (int f = tid; f < 512; f += nthr) {
        int c = f & 63, grp = f >> 6;
        int s0 = grp*8;
        float v[8];
#pragma unroll
        for (int j = 0; j < 8; j++) v[j] = src[(s0+j)*64 + c];
        u32 h[4], l[4];
#pragma unroll
        for (int i = 0; i < 4; i++) bfsplit(v[2*i], v[2*i+1], h[i], l[i]);
        *(uint4*)(Dh + c*PW + 4*grp) = make_uint4(h[0], h[1], h[2], h[3]);
        *(uint4*)(Dl + c*PW + 4*grp) = make_uint4(l[0], l[1], l[2], l[3]);
    }
}

// ---------------- plain FFMA2 64x64 matmul core ----------------
__device__ __forceinline__ void mm64_core(const float* __restrict__ A,
                                          const float* __restrict__ B,
                                          int rq, int cq, u64t acc[4][2]) {
#pragma unroll
    for (int k = 0; k < 64; k++) {
        u64t b0 = *(const u64t*)(B + k*PB + 2*cq);
        u64t b1 = *(const u64t*)(B + k*PB + 2*cq + 32);
#pragma unroll
        for (int r = 0; r < 4; r++) {
            float a = A[(rq + 16*r)*PB + k];
            u64t a2 = pk2(a, a);
            acc[r][0] = ffma2(a2, b0, acc[r][0]);
            acc[r][1] = ffma2(a2, b1, acc[r][1]);
        }
    }
}
__device__ __noinline__ void mm64_smem(const float* __restrict__ A,
                                       const float* __restrict__ B,
                                       float* __restrict__ C, int tid) {
    int cq = tid & 15, rq = tid >> 4;
    u64t acc[4][2] = {};
    mm64_core(A, B, rq, cq, acc);
#pragma unroll
    for (int r = 0; r < 4; r++) {
        *(u64t*)(C + (rq+16*r)*PB + 2*cq)      = acc[r][0];
        *(u64t*)(C + (rq+16*r)*PB + 2*cq + 32) = acc[r][1];
    }
}
__device__ __forceinline__ void tr_write(float* Ct, int rq, int cq, float aI, float bS,
                                         const u64t acc[4][2]) {
    int j0 = 2*cq, j2 = 2*cq + 32;
#pragma unroll
    for (int r = 0; r < 4; r++) {
        int row = rq + 16*r;
        float v0, v1, v2, v3;
        asm("mov.b64 {%0, %1}, %2;" : "=f"(v0), "=f"(v1) : "l"(acc[r][0]));
        asm("mov.b64 {%0, %1}, %2;" : "=f"(v2), "=f"(v3) : "l"(acc[r][1]));
        float t0 = (row == j0   ? aI : 0.f) - bS*v0;
        float t1 = (row == j0+1 ? aI : 0.f) - bS*v1;
        float t2 = (row == j2   ? aI : 0.f) - bS*v2;
        float t3 = (row == j2+1 ? aI : 0.f) - bS*v3;
        *(u64t*)(Ct + row*PB + j0) = pk2(t0, t1);
        *(u64t*)(Ct + row*PB + j2) = pk2(t2, t3);
    }
}
__device__ __forceinline__ void raw_write(float* C, int rq, int cq, const u64t acc[4][2]) {
#pragma unroll
    for (int r = 0; r < 4; r++) {
        int row = rq + 16*r;
        *(u64t*)(C + row*PB + 2*cq)      = acc[r][0];
        *(u64t*)(C + row*PB + 2*cq + 32) = acc[r][1];
    }
}

// ---------------- pooling (float4 loads) ----------------
__global__ void __launch_bounds__(256) pool_kernel(const float* __restrict__ Q,
                                                   const float* __restrict__ K) {
    int bh = blockIdx.x >> 6, lm = blockIdx.x & 63;
    int tid = threadIdx.x;
    int q = tid & 15, rg = tid >> 4;
    const float* qb = Q + ((size_t)bh*SQ + lm*64)*64;
    const float* kb = K + ((size_t)bh*SQ + lm*64)*64;
    float4 sq = {0.f,0.f,0.f,0.f}, sk = {0.f,0.f,0.f,0.f};
#pragma unroll
    for (int r = rg; r < 64; r += 16) {
        float4 a = *(const float4*)(qb + r*64 + 4*q);
        float4 b = *(const float4*)(kb + r*64 + 4*q);
        sq.x += a.x; sq.y += a.y; sq.z += a.z; sq.w += a.w;
        sk.x += b.x; sk.y += b.y; sk.z += b.z; sk.w += b.w;
    }
    __shared__ float4 shq[16][16], shk[16][16];
    shq[rg][q] = sq; shk[rg][q] = sk;
    __syncthreads();
    if (tid < 64) {
        int d = tid, qq = d >> 2, cc = d & 3;
        float s1 = 0.f, s2 = 0.f;
#pragma unroll
        for (int i = 0; i < 16; i++) {
            s1 += ((const float*)&shq[i][qq])[cc];
            s2 += ((const float*)&shk[i][qq])[cc];
        }
        float qv = s1 * (1.0f/512.0f);   // mean * 0.125
        float kv = s2 * (1.0f/64.0f);
        g_Qlm [bh*4096 + lm*64 + d] = qv;
        g_Klm [bh*4096 + lm*64 + d] = kv;
        g_KlmT[bh*4096 + d*64 + lm] = kv;
    }
}

// ---------------- Newton-Schulz body: 4 buffers, exact fp32 trajectory ----------------
__device__ void newton_body(float* sm, int bh) {
    float* A = sm;
    float* X = sm + 1*64*PB;
    float* Y = sm + 2*64*PB;
    float* Z = sm + 3*64*PB;
    __shared__ float nsred[256], nsrow[64], nscol[64], nscale[1];
    int tid = threadIdx.x;
    int cq = tid & 15, rq = tid >> 4;

    for (int idx = tid; idx < 4096; idx += 256) {
        int i = idx >> 6, k = idx & 63;
        Y[i*PB + k] = g_Qlm[bh*4096 + idx];
        Z[i*PB + k] = g_KlmT[bh*4096 + idx];
    }
    __syncthreads();
    mm64_smem(Y, Z, A, tid);
    __syncthreads();
    {
        int q = tid & 3, r = tid >> 2;
        float* Lr = A + r*PB + q*16;
        float mt = Lr[0];
#pragma unroll
        for (int c = 1; c < 16; c++) mt = fmaxf(mt, Lr[c]);
        nsred[tid] = mt; __syncthreads();
        float m = fmaxf(fmaxf(nsred[r*4], nsred[r*4+1]), fmaxf(nsred[r*4+2], nsred[r*4+3]));
        float ps = 0.f;
#pragma unroll
        for (int c = 0; c < 16; c++) { float e = __expf(Lr[c] - m); Lr[c] = e; ps += e; }
        __syncthreads();
        nsred[tid] = ps; __syncthreads();
        float inv = 1.0f / (nsred[r*4] + nsred[r*4+1] + nsred[r*4+2] + nsred[r*4+3]);
#pragma unroll
        for (int c = 0; c < 16; c++) Lr[c] *= inv;
    }
    __syncthreads();
    if (tid < 64)       { float s = 0.f; for (int j = 0; j < 64; j++) s += A[tid*PB + j]; nsrow[tid] = s; }
    else if (tid < 128) { int c = tid - 64; float s = 0.f; for (int i = 0; i < 64; i++) s += A[i*PB + c]; nscol[c] = s; }
    __syncthreads();
    if (tid == 0) {
        float mr = nsrow[0], mc = nscol[0];
        for (int i = 1; i < 64; i++) { mr = fmaxf(mr, nsrow[i]); mc = fmaxf(mc, nscol[i]); }
        nscale[0] = 1.0f / (mr * mc);
    }
    __syncthreads();
    float sc = nscale[0];
    for (int idx = tid; idx < 4096; idx += 256) {
        int i = idx >> 6, j = idx & 63;
        X[j*PB + i] = A[i*PB + j] * sc;
    }
    __syncthreads();

    float *Vb = X, *F1 = Y, *F2 = Z;
#pragma unroll 1
    for (int it = 0; it < 6; it++) {
        {
            u64t acc[4][2] = {};
            mm64_core(A, Vb, rq, cq, acc);
            raw_write(F1, rq, cq, acc);
            tr_write(F2, rq, cq, 7.0f, 1.0f, acc);
        }
        __syncthreads();
        {
            u64t acc[4][2] = {};
            mm64_core(F1, F2, rq, cq, acc);
            __syncthreads();
            tr_write(F2, rq, cq, 15.0f, 1.0f, acc);
        }
        __syncthreads();
        {
            u64t acc[4][2] = {};
            mm64_core(F1, F2, rq, cq, acc);
            __syncthreads();
            tr_write(F1, rq, cq, 3.25f, 0.25f, acc);
        }
        __syncthreads();
        {
            u64t acc[4][2] = {};
            mm64_core(Vb, F1, rq, cq, acc);
            raw_write(F2, rq, cq, acc);
        }
        __syncthreads();
        float* nv = F2; F2 = F1; F1 = Vb; Vb = nv;
    }
    for (int idx = tid; idx < 4096; idx += 256) {
        int i = idx >> 6, j = idx & 63;
        g_Inv[bh*4096 + idx] = Vb[i*PB + j];
    }
}

// ---------------- kc body: 2 groups x 4 warps, M=16/warp, P in registers ----------------
__device__ void kc_body(const float* __restrict__ K, const float* __restrict__ V,
                        u32* sm, int sp, int bh) {
    u32* Qlh = sm;
    u32* Qll = sm + 64*PW;
    int tid = threadIdx.x;
    int ss = tid >> 7, stid = tid & 127;
    int w = stid >> 5, lane = tid & 31;
    int g = lane >> 2, t = lane & 3;
    u32* Kh = sm + 2*64*PW + ss*4*64*PW;
    u32* Kl = Kh + 64*PW;
    u32* Vh = Kl + 64*PW;
    u32* Vl = Vh + 64*PW;

    stage_k(Qlh, Qll, g_Qlm + bh*4096, 64, tid, 256, 1.0f);   // already *0.125
    __syncthreads();

    int base = w*16;
    int barid = ss + 1;
    float acc[8][4] = {};
    float rs0 = 0.f, rs1 = 0.f;

#pragma unroll 1
    for (int it = 0; it < 4; it++) {
        int s0 = sp*512 + ss*256 + it*64;
        stage_k(Kh, Kl, K + ((size_t)bh*SQ + s0)*64, 64, stid, 128, 1.0f);
        stage_v(Vh, Vl, V + ((size_t)bh*SQ + s0)*64, stid, 128);
        asm volatile("bar.sync %0, %1;" :: "r"(barid), "r"(128) : "memory");

        float c[8][4] = {};
        wgemm16(Qlh, Qll, base, Kh, Kl, lane, c);   // logits[16 lm][64 s]

#pragma unroll
        for (int n = 0; n < 8; n++) {
            c[n][0] = __expf(c[n][0]); c[n][1] = __expf(c[n][1]);
            c[n][2] = __expf(c[n][2]); c[n][3] = __expf(c[n][3]);
            rs0 += c[n][0] + c[n][1];
            rs1 += c[n][2] + c[n][3];
        }
        wgemm16_regA(c, Vh, Vl, lane, acc);         // acc += P @ V (P from regs)
        asm volatile("bar.sync %0, %1;" :: "r"(barid), "r"(128) : "memory");
    }

    rs0 += __shfl_xor_sync(0xffffffffu, rs0, 1);
    rs0 += __shfl_xor_sync(0xffffffffu, rs0, 2);
    rs1 += __shfl_xor_sync(0xffffffffu, rs1, 1);
    rs1 += __shfl_xor_sync(0xffffffffu, rs1, 2);

    int osp = sp*2 + ss;
    size_t pb = ((size_t)osp*BHN + bh)*4096;
    int r0 = base + g;
#pragma unroll
    for (int nt = 0; nt < 8; nt++) {
        int col = 8*nt + 2*t;
        *(float2*)(g_pacc + pb + r0*64 + col)     = make_float2(acc[nt][0], acc[nt][1]);
        *(float2*)(g_pacc + pb + (r0+8)*64 + col) = make_float2(acc[nt][2], acc[nt][3]);
    }
    if (t == 0) {
        float* ps = g_psum + (osp*BHN+bh)*64;
        ps[r0]     = rs0;
        ps[r0 + 8] = rs1;
    }
}

__global__ void __launch_bounds__(256, 2) mega_kernel(const float* __restrict__ K,
                                                      const float* __restrict__ V) {
    extern __shared__ __align__(16) u32 smg[];
    if (blockIdx.x < 64) newton_body((float*)smg, blockIdx.x);
    else { int id = blockIdx.x - 64; kc_body(K, V, smg, id & 7, id >> 3); }
}

// ---------------- reduce splits -> F, W = Inv@F, store W^T ----------------
__global__ void __launch_bounds__(256) reduce_winv_kernel() {
    extern __shared__ __align__(16) float smr[];
    float* Fs = smr;
    float* Iv = smr + 64*PB;
    int bh = blockIdx.x, tid = threadIdx.x;

    for (int idx = tid; idx < 4096; idx += 256)
        Iv[(idx>>6)*PB + (idx&63)] = g_Inv[bh*4096 + idx];

    int d = tid & 63, ig = tid >> 6;
    for (int i = ig; i < 64; i += 4) {
        float tot = 0.f;
#pragma unroll
        for (int s = 0; s < NS2; s++) tot += g_psum[(s*BHN+bh)*64 + i];
        float v = 0.f;
#pragma unroll
        for (int s = 0; s < NS2; s++)
            v += g_pacc[((size_t)s*BHN+bh)*4096 + i*64 + d];
        Fs[i*PB + d] = v / tot;
    }
    __syncthreads();
    int cq = tid & 15, rq = tid >> 4;
    u64t acc[4][2] = {};
    mm64_core(Iv, Fs, rq, cq, acc);
    float* wt = g_WT + (size_t)bh*4096;
#pragma unroll
    for (int rr = 0; rr < 4; rr++) {
        int row = rq + 16*rr;
        float v0, v1, v2, v3;
        asm("mov.b64 {%0, %1}, %2;" : "=f"(v0), "=f"(v1) : "l"(acc[rr][0]));
        asm("mov.b64 {%0, %1}, %2;" : "=f"(v2), "=f"(v3) : "l"(acc[rr][1]));
        wt[(2*cq)*64    + row] = v0;
        wt[(2*cq+1)*64  + row] = v1;
        wt[(2*cq+32)*64 + row] = v2;
        wt[(2*cq+33)*64 + row] = v3;
    }
}

// ---------------- kd: 8 warps, M=16/warp, 2 tiles/CTA, P stays in regs ----------------
__global__ void __launch_bounds__(256, 3) kd_bf(const float* __restrict__ Q,
                                                float* __restrict__ X) {
    extern __shared__ __align__(16) u32 smk[];
    u32* Qh = smk;
    u32* Ql = Qh + 128*PW;
    u32* Kh = Ql + 128*PW;
    u32* Kl = Kh + 64*PW;
    u32* Wh = Kl + 64*PW;
    u32* Wl = Wh + 64*PW;
    int tid = threadIdx.x, lane = tid & 31, wid = tid >> 5;
    int g = lane >> 2, t = lane & 3;
    int bh = blockIdx.y;

    stage_k(Kh, Kl, g_Klm + (size_t)bh*4096, 64, tid, 256, 1.0f);
    stage_k(Wh, Wl, g_WT  + (size_t)bh*4096, 64, tid, 256, 1.0f);

    int base = wid*16;
    int r0 = base + g;

#pragma unroll 1
    for (int t2 = 0; t2 < 2; t2++) {
        int tile = blockIdx.x*2 + t2;
        if (t2) __syncthreads();    // all MMA1 Q reads done before restage
        stage_k(Qh, Ql, Q + ((size_t)bh*SQ + tile*128)*64, 128, tid, 256, 0.125f);
        __syncthreads();

        float c[8][4];
#pragma unroll
        for (int n = 0; n < 8; n++) { c[n][0]=0.f; c[n][1]=0.f; c[n][2]=0.f; c[n][3]=0.f; }
        wgemm16(Qh, Ql, base, Kh, Kl, lane, c);   // logits [tok][lm]

        float rs0 = 0.f, rs1 = 0.f;
#pragma unroll
        for (int n = 0; n < 8; n++) {
            c[n][0] = __expf(c[n][0]); c[n][1] = __expf(c[n][1]);
            c[n][2] = __expf(c[n][2]); c[n][3] = __expf(c[n][3]);
            rs0 += c[n][0] + c[n][1];
            rs1 += c[n][2] + c[n][3];
        }
        rs0 += __shfl_xor_sync(0xffffffffu, rs0, 1);
        rs0 += __shfl_xor_sync(0xffffffffu, rs0, 2);
        rs1 += __shfl_xor_sync(0xffffffffu, rs1, 1);
        rs1 += __shfl_xor_sync(0xffffffffu, rs1, 2);
        float rinv0 = 1.0f / rs0, rinv1 = 1.0f / rs1;

        float d[8][4];
#pragma unroll
        for (int n = 0; n < 8; n++) { d[n][0]=0.f; d[n][1]=0.f; d[n][2]=0.f; d[n][3]=0.f; }
        wgemm16_regA(c, Wh, Wl, lane, d);         // X~ = P @ W (P from regs)

        float* x0 = X + ((size_t)bh*SQ + tile*128)*64;
#pragma unroll
        for (int nt = 0; nt < 8; nt++) {
            int col = 8*nt + 2*t;
            *(float2*)(x0 + r0*64 + col)     = make_float2(d[nt][0]*rinv0, d[nt][1]*rinv0);
            *(float2*)(x0 + (r0+8)*64 + col) = make_float2(d[nt][2]*rinv1, d[nt][3]*rinv1);
        }
    }
}

// ---------------- launcher ----------------
extern "C" void kernel_launch(void* const* d_in, const int* in_sizes, int n_in,
                              void* d_out, int out_size) {
    (void)in_sizes; (void)n_in; (void)out_size;
    const float* Q = (const float*)d_in[0];
    const float* K = (const float*)d_in[1];
    const float* V = (const float*)d_in[2];
    float* X = (float*)d_out;

    const int SMEM_MEGA = 10*64*PW*4;   // 92160 (kc); newton uses 69632 -> 2 CTAs/SM
    const int SMEM_RW   = 2*64*PB*4;    // 34816
    const int SMEM_KD   = 512*PW*4;     // 73728 -> 3 CTAs/SM
    cudaFuncSetAttribute(mega_kernel,        cudaFuncAttributeMaxDynamicSharedMemorySize, SMEM_MEGA);
    cudaFuncSetAttribute(reduce_winv_kernel, cudaFuncAttributeMaxDynamicSharedMemorySize, SMEM_RW);
    cudaFuncSetAttribute(kd_bf,              cudaFuncAttributeMaxDynamicSharedMemorySize, SMEM_KD);

    pool_kernel<<<BHN*64, 256>>>(Q, K);
    mega_kernel<<<64 + 8*BHN, 256, SMEM_MEGA>>>(K, V);
    reduce_winv_kernel<<<BHN, 256, SMEM_RW>>>();
    kd_bf<<<dim3(16, BHN), 256, SMEM_KD>>>(Q, X);
}

// round 16
// speedup vs baseline: 1.2461x; 1.0343x over previous
#include <cuda_runtime.h>
#include <cuda_bf16.h>
#include <cstdint>

#define SQ   4096
#define BHN  64
#define PB   68     // fp32 smem pitch (floats)
#define PW   36     // packed bf16x2 word pitch
#define NS2  16     // softmax splits

typedef unsigned long long u64t;
typedef unsigned int u32;

// ---------------- scratch ----------------
__device__ float g_Qlm [BHN*64*64];
__device__ float g_KlmT[BHN*64*64];
__device__ float g_Klm [BHN*64*64];
__device__ float g_Inv [BHN*64*64];
__device__ float g_WT  [BHN*64*64];   // (inv@F)^T : [d][m]
__device__ float g_pacc[(size_t)NS2*BHN*64*64];
__device__ float g_psum[NS2*BHN*64];

// ---------------- scalar helpers ----------------
__device__ __forceinline__ u64t pk2(float lo, float hi) {
    u64t r; asm("mov.b64 %0, {%1, %2};" : "=l"(r) : "f"(lo), "f"(hi)); return r;
}
__device__ __forceinline__ u64t ffma2(u64t a, u64t b, u64t c) {
    u64t d; asm("fma.rn.f32x2 %0, %1, %2, %3;" : "=l"(d) : "l"(a), "l"(b), "l"(c)); return d;
}
__device__ __forceinline__ u32 bfpack(float x, float y) {
    __nv_bfloat162 h = __floats2bfloat162_rn(x, y);
    return *reinterpret_cast<u32*>(&h);
}
__device__ __forceinline__ void bfsplit(float x, float y, u32& hw, u32& lw) {
    __nv_bfloat162 h = __floats2bfloat162_rn(x, y);
    float hx = __bfloat162float(h.x), hy = __bfloat162float(h.y);
    hw = *reinterpret_cast<u32*>(&h);
    lw = bfpack(x - hx, y - hy);
}
__device__ __forceinline__ void mmab(float c[4], u32 a0, u32 a1, u32 a2, u32 a3,
                                     u32 b0, u32 b1) {
    asm volatile("mma.sync.aligned.m16n8k16.row.col.f32.bf16.bf16.f32 "
        "{%0,%1,%2,%3}, {%4,%5,%6,%7}, {%8,%9}, {%0,%1,%2,%3};"
        : "+f"(c[0]), "+f"(c[1]), "+f"(c[2]), "+f"(c[3])
        : "r"(a0), "r"(a1), "r"(a2), "r"(a3), "r"(b0), "r"(b1));
}
__device__ __forceinline__ u32 sptr(const void* p) {
    u32 a;
    asm("{ .reg .u64 t; cvta.to.shared.u64 t, %1; cvt.u32.u64 %0, t; }" : "=r"(a) : "l"(p));
    return a;
}
__device__ __forceinline__ void ldsm4(u32* r, u32 addr) {
    asm volatile("ldmatrix.sync.aligned.m8n8.x4.shared.b16 {%0,%1,%2,%3}, [%4];"
        : "=r"(r[0]), "=r"(r[1]), "=r"(r[2]), "=r"(r[3]) : "r"(addr));
}

// warp gemm: C[16x32] += A[16 rows, k=64] @ B[n = nbase..nbase+31, k=64]  (kc MMA1)
__device__ __forceinline__ void wg16x32(const u32* __restrict__ Ah, const u32* __restrict__ Al,
                                        int base,
                                        const u32* __restrict__ Bh, const u32* __restrict__ Bl,
                                        int nbase, int lane, float c[4][4]) {
    int mi = lane >> 3, lr = lane & 7;
    u32 aH = sptr(Ah + (base + (mi & 1)*8 + lr)*PW + (mi >> 1)*4);
    u32 aL = sptr(Al + (base + (mi & 1)*8 + lr)*PW + (mi >> 1)*4);
    u32 bH = sptr(Bh + (nbase + (mi >> 1)*8 + lr)*PW + (mi & 1)*4);
    u32 bL = sptr(Bl + (nbase + (mi >> 1)*8 + lr)*PW + (mi & 1)*4);
#pragma unroll
    for (int kt = 0; kt < 4; kt++) {
        u32 ah[4], al[4];
        ldsm4(ah, aH + kt*32);
        ldsm4(al, aL + kt*32);
#pragma unroll
        for (int p = 0; p < 2; p++) {
            u32 bh[4], bl[4];
            ldsm4(bh, bH + p*(16*PW*4) + kt*32);
            ldsm4(bl, bL + p*(16*PW*4) + kt*32);
            mmab(c[2*p],   ah[0],ah[1],ah[2],ah[3], bh[0],bh[1]);
            mmab(c[2*p],   al[0],al[1],al[2],al[3], bh[0],bh[1]);
            mmab(c[2*p],   ah[0],ah[1],ah[2],ah[3], bl[0],bl[1]);
            mmab(c[2*p+1], ah[0],ah[1],ah[2],ah[3], bh[2],bh[3]);
            mmab(c[2*p+1], al[0],al[1],al[2],al[3], bh[2],bh[3]);
            mmab(c[2*p+1], ah[0],ah[1],ah[2],ah[3], bl[2],bl[3]);
        }
    }
}

// MMA2 from register P (kc): d[16x64] += P(c regs, k=32) @ B[64 n, k=32 at word off co]
__device__ __forceinline__ void wg_regA_k32(const float c[4][4],
                                            const u32* __restrict__ Bh,
                                            const u32* __restrict__ Bl, int co,
                                            int lane, float d[8][4]) {
    int mi = lane >> 3, lr = lane & 7;
    u32 bH = sptr(Bh + ((mi >> 1)*8 + lr)*PW + (mi & 1)*4 + co);
    u32 bL = sptr(Bl + ((mi >> 1)*8 + lr)*PW + (mi & 1)*4 + co);
#pragma unroll
    for (int kt = 0; kt < 2; kt++) {
        u32 ah0, al0, ah1, al1, ah2, al2, ah3, al3;
        bfsplit(c[2*kt][0],   c[2*kt][1],   ah0, al0);
        bfsplit(c[2*kt][2],   c[2*kt][3],   ah1, al1);
        bfsplit(c[2*kt+1][0], c[2*kt+1][1], ah2, al2);
        bfsplit(c[2*kt+1][2], c[2*kt+1][3], ah3, al3);
#pragma unroll
        for (int p = 0; p < 4; p++) {
            u32 bh[4], bl[4];
            ldsm4(bh, bH + p*(16*PW*4) + kt*32);
            ldsm4(bl, bL + p*(16*PW*4) + kt*32);
            mmab(d[2*p],   ah0,ah1,ah2,ah3, bh[0],bh[1]);
            mmab(d[2*p],   al0,al1,al2,al3, bh[0],bh[1]);
            mmab(d[2*p],   ah0,ah1,ah2,ah3, bl[0],bl[1]);
            mmab(d[2*p+1], ah0,ah1,ah2,ah3, bh[2],bh[3]);
            mmab(d[2*p+1], al0,al1,al2,al3, bh[2],bh[3]);
            mmab(d[2*p+1], ah0,ah1,ah2,ah3, bl[2],bl[3]);
        }
    }
}

// MMA2 from register P (kd): d[16x64] += P(c regs, k=64) @ B[64 n, k=64]
__device__ __forceinline__ void wgemm16_regA(const float c[8][4],
                                             const u32* __restrict__ Bh,
                                             const u32* __restrict__ Bl,
                                             int lane, float d[8][4]) {
    int mi = lane >> 3, lr = lane & 7;
    u32 bH = sptr(Bh + ((mi >> 1)*8 + lr)*PW + (mi & 1)*4);
    u32 bL = sptr(Bl + ((mi >> 1)*8 + lr)*PW + (mi & 1)*4);
#pragma unroll
    for (int kt = 0; kt < 4; kt++) {
        u32 ah0, al0, ah1, al1, ah2, al2, ah3, al3;
        bfsplit(c[2*kt][0],   c[2*kt][1],   ah0, al0);
        bfsplit(c[2*kt][2],   c[2*kt][3],   ah1, al1);
        bfsplit(c[2*kt+1][0], c[2*kt+1][1], ah2, al2);
        bfsplit(c[2*kt+1][2], c[2*kt+1][3], ah3, al3);
#pragma unroll
        for (int p = 0; p < 4; p++) {
            u32 bh[4], bl[4];
            ldsm4(bh, bH + p*(16*PW*4) + kt*32);
            ldsm4(bl, bL + p*(16*PW*4) + kt*32);
            mmab(d[2*p],   ah0,ah1,ah2,ah3, bh[0],bh[1]);
            mmab(d[2*p],   al0,al1,al2,al3, bh[0],bh[1]);
            mmab(d[2*p],   ah0,ah1,ah2,ah3, bl[0],bl[1]);
            mmab(d[2*p+1], ah0,ah1,ah2,ah3, bh[2],bh[3]);
            mmab(d[2*p+1], al0,al1,al2,al3, bh[2],bh[3]);
            mmab(d[2*p+1], ah0,ah1,ah2,ah3, bl[2],bl[3]);
        }
    }
}

// kd MMA1: A fragments loaded directly from gmem (rows r0, r0+8), scale folded
__device__ __forceinline__ void wgemm16_gmemA(const float* __restrict__ qr0,
                                              const u32* __restrict__ Bh,
                                              const u32* __restrict__ Bl,
                                              int lane, float c[8][4]) {
    int t = lane & 3;
    int mi = lane >> 3, lr = lane & 7;
    u32 bH = sptr(Bh + ((mi >> 1)*8 + lr)*PW + (mi & 1)*4);
    u32 bL = sptr(Bl + ((mi >> 1)*8 + lr)*PW + (mi & 1)*4);
#pragma unroll
    for (int kt = 0; kt < 4; kt++) {
        const float* qp = qr0 + kt*16 + 2*t;
        float2 q00 = *(const float2*)(qp);
        float2 q20 = *(const float2*)(qp + 8);
        float2 q01 = *(const float2*)(qp + 512);       // row +8
        float2 q21 = *(const float2*)(qp + 520);
        u32 ah0, al0, ah1, al1, ah2, al2, ah3, al3;
        bfsplit(q00.x*0.125f, q00.y*0.125f, ah0, al0);
        bfsplit(q01.x*0.125f, q01.y*0.125f, ah1, al1);
        bfsplit(q20.x*0.125f, q20.y*0.125f, ah2, al2);
        bfsplit(q21.x*0.125f, q21.y*0.125f, ah3, al3);
#pragma unroll
        for (int p = 0; p < 4; p++) {
            u32 bh[4], bl[4];
            ldsm4(bh, bH + p*(16*PW*4) + kt*32);
            ldsm4(bl, bL + p*(16*PW*4) + kt*32);
            mmab(c[2*p],   ah0,ah1,ah2,ah3, bh[0],bh[1]);
            mmab(c[2*p],   al0,al1,al2,al3, bh[0],bh[1]);
            mmab(c[2*p],   ah0,ah1,ah2,ah3, bl[0],bl[1]);
            mmab(c[2*p+1], ah0,ah1,ah2,ah3, bh[2],bh[3]);
            mmab(c[2*p+1], al0,al1,al2,al3, bh[2],bh[3]);
            mmab(c[2*p+1], ah0,ah1,ah2,ah3, bl[2],bl[3]);
        }
    }
}

// stage row-major fp32 [rows][64] -> packed along k
__device__ __forceinline__ void stage_k(u32* Dh, u32* Dl, const float* __restrict__ src,
                                        int rows, int tid, int nthr, float scale) {
    for (int f = tid; f < rows*16; f += nthr) {
        int r = f >> 4, q = f & 15;
        float4 v = *(const float4*)(src + r*64 + 4*q);
        v.x *= scale; v.y *= scale; v.z *= scale; v.w *= scale;
        u32 h0, l0, h1, l1;
        bfsplit(v.x, v.y, h0, l0);
        bfsplit(v.z, v.w, h1, l1);
        *(u64t*)(Dh + r*PW + 2*q) = (u64t)h0 | ((u64t)h1 << 32);
        *(u64t*)(Dl + r*PW + 2*q) = (u64t)l0 | ((u64t)l1 << 32);
    }
}

// stage V [64 s][64 d] -> packed along s
__device__ __forceinline__ void stage_v(u32* Dh, u32* Dl, const float* __restrict__ src,
                                        int tid, int nthr) {
    for (int f = tid; f < 512; f += nthr) {
        int c = f & 63, grp = f >> 6;
        int s0 = grp*8;
        float v[8];
#pragma unroll
        for (int j = 0; j < 8; j++) v[j] = src[(s0+j)*64 + c];
        u32 h[4], l[4];
#pragma unroll
        for (int i = 0; i < 4; i++) bfsplit(v[2*i], v[2*i+1], h[i], l[i]);
        *(uint4*)(Dh + c*PW + 4*grp) = make_uint4(h[0], h[1], h[2], h[3]);
        *(uint4*)(Dl + c*PW + 4*grp) = make_uint4(l[0], l[1], l[2], l[3]);
    }
}

// ---------------- plain FFMA2 64x64 matmul core ----------------
__device__ __forceinline__ void mm64_core(const float* __restrict__ A,
                                          const float* __restrict__ B,
                                          int rq, int cq, u64t acc[4][2]) {
#pragma unroll
    for (int k = 0; k < 64; k++) {
        u64t b0 = *(const u64t*)(B + k*PB + 2*cq);
        u64t b1 = *(const u64t*)(B + k*PB + 2*cq + 32);
#pragma unroll
        for (int r = 0; r < 4; r++) {
            float a = A[(rq + 16*r)*PB + k];
            u64t a2 = pk2(a, a);
            acc[r][0] = ffma2(a2, b0, acc[r][0]);
            acc[r][1] = ffma2(a2, b1, acc[r][1]);
        }
    }
}
__device__ __noinline__ void mm64_smem(const float* __restrict__ A,
                                       const float* __restrict__ B,
                                       float* __restrict__ C, int tid) {
    int cq = tid & 15, rq = tid >> 4;
    u64t acc[4][2] = {};
    mm64_core(A, B, rq, cq, acc);
#pragma unroll
    for (int r = 0; r < 4; r++) {
        *(u64t*)(C + (rq+16*r)*PB + 2*cq)      = acc[r][0];
        *(u64t*)(C + (rq+16*r)*PB + 2*cq + 32) = acc[r][1];
    }
}
__device__ __forceinline__ void tr_write(float* Ct, int rq, int cq, float aI, float bS,
                                         const u64t acc[4][2]) {
    int j0 = 2*cq, j2 = 2*cq + 32;
#pragma unroll
    for (int r = 0; r < 4; r++) {
        int row = rq + 16*r;
        float v0, v1, v2, v3;
        asm("mov.b64 {%0, %1}, %2;" : "=f"(v0), "=f"(v1) : "l"(acc[r][0]));
        asm("mov.b64 {%0, %1}, %2;" : "=f"(v2), "=f"(v3) : "l"(acc[r][1]));
        float t0 = (row == j0   ? aI : 0.f) - bS*v0;
        float t1 = (row == j0+1 ? aI : 0.f) - bS*v1;
        float t2 = (row == j2   ? aI : 0.f) - bS*v2;
        float t3 = (row == j2+1 ? aI : 0.f) - bS*v3;
        *(u64t*)(Ct + row*PB + j0) = pk2(t0, t1);
        *(u64t*)(Ct + row*PB + j2) = pk2(t2, t3);
    }
}
__device__ __forceinline__ void raw_write(float* C, int rq, int cq, const u64t acc[4][2]) {
#pragma unroll
    for (int r = 0; r < 4; r++) {
        int row = rq + 16*r;
        *(u64t*)(C + row*PB + 2*cq)      = acc[r][0];
        *(u64t*)(C + row*PB + 2*cq + 32) = acc[r][1];
    }
}

// ---------------- pooling (float4 loads) ----------------
__global__ void __launch_bounds__(256) pool_kernel(const float* __restrict__ Q,
                                                   const float* __restrict__ K) {
    int bh = blockIdx.x >> 6, lm = blockIdx.x & 63;
    int tid = threadIdx.x;
    int q = tid & 15, rg = tid >> 4;
    const float* qb = Q + ((size_t)bh*SQ + lm*64)*64;
    const float* kb = K + ((size_t)bh*SQ + lm*64)*64;
    float4 sq = {0.f,0.f,0.f,0.f}, sk = {0.f,0.f,0.f,0.f};
#pragma unroll
    for (int r = rg; r < 64; r += 16) {
        float4 a = *(const float4*)(qb + r*64 + 4*q);
        float4 b = *(const float4*)(kb + r*64 + 4*q);
        sq.x += a.x; sq.y += a.y; sq.z += a.z; sq.w += a.w;
        sk.x += b.x; sk.y += b.y; sk.z += b.z; sk.w += b.w;
    }
    __shared__ float4 shq[16][16], shk[16][16];
    shq[rg][q] = sq; shk[rg][q] = sk;
    __syncthreads();
    if (tid < 64) {
        int d = tid, qq = d >> 2, cc = d & 3;
        float s1 = 0.f, s2 = 0.f;
#pragma unroll
        for (int i = 0; i < 16; i++) {
            s1 += ((const float*)&shq[i][qq])[cc];
            s2 += ((const float*)&shk[i][qq])[cc];
        }
        float qv = s1 * (1.0f/512.0f);
        float kv = s2 * (1.0f/64.0f);
        g_Qlm [bh*4096 + lm*64 + d] = qv;
        g_Klm [bh*4096 + lm*64 + d] = kv;
        g_KlmT[bh*4096 + d*64 + lm] = kv;
    }
}

// ---------------- Newton-Schulz body: 4 buffers, exact fp32 trajectory ----------------
__device__ void newton_body(float* sm, int bh) {
    float* A = sm;
    float* X = sm + 1*64*PB;
    float* Y = sm + 2*64*PB;
    float* Z = sm + 3*64*PB;
    __shared__ float nsred[256], nsrow[64], nscol[64], nscale[1];
    int tid = threadIdx.x;
    int cq = tid & 15, rq = tid >> 4;

    for (int idx = tid; idx < 4096; idx += 256) {
        int i = idx >> 6, k = idx & 63;
        Y[i*PB + k] = g_Qlm[bh*4096 + idx];
        Z[i*PB + k] = g_KlmT[bh*4096 + idx];
    }
    __syncthreads();
    mm64_smem(Y, Z, A, tid);
    __syncthreads();
    {
        int q = tid & 3, r = tid >> 2;
        float* Lr = A + r*PB + q*16;
        float mt = Lr[0];
#pragma unroll
        for (int c = 1; c < 16; c++) mt = fmaxf(mt, Lr[c]);
        nsred[tid] = mt; __syncthreads();
        float m = fmaxf(fmaxf(nsred[r*4], nsred[r*4+1]), fmaxf(nsred[r*4+2], nsred[r*4+3]));
        float ps = 0.f;
#pragma unroll
        for (int c = 0; c < 16; c++) { float e = __expf(Lr[c] - m); Lr[c] = e; ps += e; }
        __syncthreads();
        nsred[tid] = ps; __syncthreads();
        float inv = 1.0f / (nsred[r*4] + nsred[r*4+1] + nsred[r*4+2] + nsred[r*4+3]);
#pragma unroll
        for (int c = 0; c < 16; c++) Lr[c] *= inv;
    }
    __syncthreads();
    if (tid < 64)       { float s = 0.f; for (int j = 0; j < 64; j++) s += A[tid*PB + j]; nsrow[tid] = s; }
    else if (tid < 128) { int c = tid - 64; float s = 0.f; for (int i = 0; i < 64; i++) s += A[i*PB + c]; nscol[c] = s; }
    __syncthreads();
    if (tid == 0) {
        float mr = nsrow[0], mc = nscol[0];
        for (int i = 1; i < 64; i++) { mr = fmaxf(mr, nsrow[i]); mc = fmaxf(mc, nscol[i]); }
        nscale[0] = 1.0f / (mr * mc);
    }
    __syncthreads();
    float sc = nscale[0];
    for (int idx = tid; idx < 4096; idx += 256) {
        int i = idx >> 6, j = idx & 63;
        X[j*PB + i] = A[i*PB + j] * sc;
    }
    __syncthreads();

    float *Vb = X, *F1 = Y, *F2 = Z;
#pragma unroll 1
    for (int it = 0; it < 6; it++) {
        {
            u64t acc[4][2] = {};
            mm64_core(A, Vb, rq, cq, acc);
            raw_write(F1, rq, cq, acc);
            tr_write(F2, rq, cq, 7.0f, 1.0f, acc);
        }
        __syncthreads();
        {
            u64t acc[4][2] = {};
            mm64_core(F1, F2, rq, cq, acc);
            __syncthreads();
            tr_write(F2, rq, cq, 15.0f, 1.0f, acc);
        }
        __syncthreads();
        {
            u64t acc[4][2] = {};
            mm64_core(F1, F2, rq, cq, acc);
            __syncthreads();
            tr_write(F1, rq, cq, 3.25f, 0.25f, acc);
        }
        __syncthreads();
        {
            u64t acc[4][2] = {};
            mm64_core(Vb, F1, rq, cq, acc);
            raw_write(F2, rq, cq, acc);
        }
        __syncthreads();
        float* nv = F2; F2 = F1; F1 = Vb; Vb = nv;
    }
    for (int idx = tid; idx < 4096; idx += 256) {
        int i = idx >> 6, j = idx & 63;
        g_Inv[bh*4096 + idx] = Vb[i*PB + j];
    }
}

// ---------------- kc body: 8 warps share one K/V tile; halves merged in-block ----------------
__device__ void kc_body(const float* __restrict__ K, const float* __restrict__ V,
                        u32* sm, int sp, int bh) {
    u32* Qlh = sm;
    u32* Qll = sm + 64*PW;
    u32* Kh  = sm + 2*64*PW;
    u32* Kl  = sm + 3*64*PW;
    u32* Vh  = sm + 4*64*PW;
    u32* Vl  = sm + 5*64*PW;
    float* xch = (float*)(sm + 2*64*PW);   // reuse K region for epilogue merge (16KB)
    __shared__ float srs[4][16];
    int tid = threadIdx.x, lane = tid & 31, wid = tid >> 5;
    int g = lane >> 2, t = lane & 3;
    int wd = wid & 3, half = wid >> 2;
    int base = wd*16, nb = half*32, co = half*16;

    stage_k(Qlh, Qll, g_Qlm + bh*4096, 64, tid, 256, 1.0f);   // already *0.125

    float acc[8][4] = {};
    float rs0 = 0.f, rs1 = 0.f;
    __syncthreads();

#pragma unroll 1
    for (int it = 0; it < 4; it++) {
        int s0 = sp*256 + it*64;
        stage_k(Kh, Kl, K + ((size_t)bh*SQ + s0)*64, 64, tid, 256, 1.0f);
        stage_v(Vh, Vl, V + ((size_t)bh*SQ + s0)*64, tid, 256);
        __syncthreads();

        float c[4][4] = {};
        wg16x32(Qlh, Qll, base, Kh, Kl, nb, lane, c);   // logits[16 lm][32 s-half]

#pragma unroll
        for (int n = 0; n < 4; n++) {
            c[n][0] = __expf(c[n][0]); c[n][1] = __expf(c[n][1]);
            c[n][2] = __expf(c[n][2]); c[n][3] = __expf(c[n][3]);
            rs0 += c[n][0] + c[n][1];
            rs1 += c[n][2] + c[n][3];
        }
        wg_regA_k32(c, Vh, Vl, co, lane, acc);          // acc += P @ V(s-half), full d
        __syncthreads();                                // K/V reads done before restage
    }

    rs0 += __shfl_xor_sync(0xffffffffu, rs0, 1);
    rs0 += __shfl_xor_sync(0xffffffffu, rs0, 2);
    rs1 += __shfl_xor_sync(0xffffffffu, rs1, 1);
    rs1 += __shfl_xor_sync(0xffffffffu, rs1, 2);

    int r0 = base + g;
    if (half == 1) {
        // dump partial O and rs for merge (K region is dead)
#pragma unroll
        for (int nt = 0; nt < 8; nt++) {
            int col = 8*nt + 2*t;
            *(float2*)(xch + r0*64 + col)     = make_float2(acc[nt][0], acc[nt][1]);
            *(float2*)(xch + (r0+8)*64 + col) = make_float2(acc[nt][2], acc[nt][3]);
        }
        if (t == 0) { srs[wd][g] = rs0; srs[wd][g + 8] = rs1; }
    }
    __syncthreads();
    if (half == 0) {
        size_t pb = ((size_t)sp*BHN + bh)*4096;
#pragma unroll
        for (int nt = 0; nt < 8; nt++) {
            int col = 8*nt + 2*t;
            float2 oA = *(const float2*)(xch + r0*64 + col);
            float2 oB = *(const float2*)(xch + (r0+8)*64 + col);
            *(float2*)(g_pacc + pb + r0*64 + col) =
                make_float2(acc[nt][0] + oA.x, acc[nt][1] + oA.y);
            *(float2*)(g_pacc + pb + (r0+8)*64 + col) =
                make_float2(acc[nt][2] + oB.x, acc[nt][3] + oB.y);
        }
        if (t == 0) {
            float* ps = g_psum + (sp*BHN + bh)*64;
            ps[r0]     = rs0 + srs[wd][g];
            ps[r0 + 8] = rs1 + srs[wd][g + 8];
        }
    }
}

__global__ void __launch_bounds__(256, 3) mega_kernel(const float* __restrict__ K,
                                                      const float* __restrict__ V) {
    extern __shared__ __align__(16) u32 smg[];
    if (blockIdx.x < 64) newton_body((float*)smg, blockIdx.x);
    else { int id = blockIdx.x - 64; kc_body(K, V, smg, id & (NS2-1), id >> 4); }
}

// ---------------- reduce splits -> F, W = Inv@F, store W^T ----------------
__global__ void __launch_bounds__(256) reduce_winv_kernel() {
    extern __shared__ __align__(16) float smr[];
    float* Fs = smr;
    float* Iv = smr + 64*PB;
    int bh = blockIdx.x, tid = threadIdx.x;

    for (int idx = tid; idx < 4096; idx += 256)
        Iv[(idx>>6)*PB + (idx&63)] = g_Inv[bh*4096 + idx];

    int d = tid & 63, ig = tid >> 6;
    for (int i = ig; i < 64; i += 4) {
        float tot = 0.f;
#pragma unroll
        for (int s = 0; s < NS2; s++) tot += g_psum[(s*BHN+bh)*64 + i];
        float v = 0.f;
#pragma unroll
        for (int s = 0; s < NS2; s++)
            v += g_pacc[((size_t)s*BHN+bh)*4096 + i*64 + d];
        Fs[i*PB + d] = v / tot;
    }
    __syncthreads();
    int cq = tid & 15, rq = tid >> 4;
    u64t acc[4][2] = {};
    mm64_core(Iv, Fs, rq, cq, acc);
    float* wt = g_WT + (size_t)bh*4096;
#pragma unroll
    for (int rr = 0; rr < 4; rr++) {
        int row = rq + 16*rr;
        float v0, v1, v2, v3;
        asm("mov.b64 {%0, %1}, %2;" : "=f"(v0), "=f"(v1) : "l"(acc[rr][0]));
        asm("mov.b64 {%0, %1}, %2;" : "=f"(v2), "=f"(v3) : "l"(acc[rr][1]));
        wt[(2*cq)*64    + row] = v0;
        wt[(2*cq+1)*64  + row] = v1;
        wt[(2*cq+32)*64 + row] = v2;
        wt[(2*cq+33)*64 + row] = v3;
    }
}

// ---------------- kd: 8 warps, M=16/warp, Q direct from gmem, P in regs ----------------
__global__ void __launch_bounds__(256, 3) kd_bf(const float* __restrict__ Q,
                                                float* __restrict__ X) {
    extern __shared__ __align__(16) u32 smk[];
    u32* Kh = smk;
    u32* Kl = Kh + 64*PW;
    u32* Wh = Kl + 64*PW;
    u32* Wl = Wh + 64*PW;
    int tid = threadIdx.x, lane = tid & 31, wid = tid >> 5;
    int g = lane >> 2, t = lane & 3;
    int bh = blockIdx.y;

    stage_k(Kh, Kl, g_Klm + (size_t)bh*4096, 64, tid, 256, 1.0f);
    stage_k(Wh, Wl, g_WT  + (size_t)bh*4096, 64, tid, 256, 1.0f);
    __syncthreads();

    int base = wid*16;
    int r0 = base + g;

#pragma unroll 1
    for (int t2 = 0; t2 < 2; t2++) {
        int tile = blockIdx.x*2 + t2;
        const float* qr0 = Q + ((size_t)bh*SQ + tile*128 + r0)*64;

        float c[8][4];
#pragma unroll
        for (int n = 0; n < 8; n++) { c[n][0]=0.f; c[n][1]=0.f; c[n][2]=0.f; c[n][3]=0.f; }
        wgemm16_gmemA(qr0, Kh, Kl, lane, c);      // logits [tok][lm], Q from gmem

        float rs0 = 0.f, rs1 = 0.f;
#pragma unroll
        for (int n = 0; n < 8; n++) {
            c[n][0] = __expf(c[n][0]); c[n][1] = __expf(c[n][1]);
            c[n][2] = __expf(c[n][2]); c[n][3] = __expf(c[n][3]);
            rs0 += c[n][0] + c[n][1];
            rs1 += c[n][2] + c[n][3];
        }
        rs0 += __shfl_xor_sync(0xffffffffu, rs0, 1);
        rs0 += __shfl_xor_sync(0xffffffffu, rs0, 2);
        rs1 += __shfl_xor_sync(0xffffffffu, rs1, 1);
        rs1 += __shfl_xor_sync(0xffffffffu, rs1, 2);
        float rinv0 = 1.0f / rs0, rinv1 = 1.0f / rs1;

        float d[8][4];
#pragma unroll
        for (int n = 0; n < 8; n++) { d[n][0]=0.f; d[n][1]=0.f; d[n][2]=0.f; d[n][3]=0.f; }
        wgemm16_regA(c, Wh, Wl, lane, d);         // X~ = P @ W (P from regs)

        float* x0 = X + ((size_t)bh*SQ + tile*128)*64;
#pragma unroll
        for (int nt = 0; nt < 8; nt++) {
            int col = 8*nt + 2*t;
            *(float2*)(x0 + r0*64 + col)     = make_float2(d[nt][0]*rinv0, d[nt][1]*rinv0);
            *(float2*)(x0 + (r0+8)*64 + col) = make_float2(d[nt][2]*rinv1, d[nt][3]*rinv1);
        }
    }
}

// ---------------- launcher ----------------
extern "C" void kernel_launch(void* const* d_in, const int* in_sizes, int n_in,
                              void* d_out, int out_size) {
    (void)in_sizes; (void)n_in; (void)out_size;
    const float* Q = (const float*)d_in[0];
    const float* K = (const float*)d_in[1];
    const float* V = (const float*)d_in[2];
    float* X = (float*)d_out;

    const int SMEM_MEGA = 4*64*PB*4;    // 69632 (newton); kc uses 55296 -> 3 CTAs/SM
    const int SMEM_RW   = 2*64*PB*4;    // 34816
    const int SMEM_KD   = 4*64*PW*4;    // 36864
    cudaFuncSetAttribute(mega_kernel,        cudaFuncAttributeMaxDynamicSharedMemorySize, SMEM_MEGA);
    cudaFuncSetAttribute(reduce_winv_kernel, cudaFuncAttributeMaxDynamicSharedMemorySize, SMEM_RW);
    cudaFuncSetAttribute(kd_bf,              cudaFuncAttributeMaxDynamicSharedMemorySize, SMEM_KD);

    pool_kernel<<<BHN*64, 256>>>(Q, K);
    mega_kernel<<<64 + NS2*BHN, 256, SMEM_MEGA>>>(K, V);
    reduce_winv_kernel<<<BHN, 256, SMEM_RW>>>();
    kd_bf<<<dim3(16, BHN), 256, SMEM_KD>>>(Q, X);
}

// round 17
// speedup vs baseline: 1.2869x; 1.0328x over previous
#include <cuda_runtime.h>
#include <cuda_bf16.h>
#include <cstdint>

#define SQ   4096
#define BHN  64
#define PB   68     // fp32 smem pitch (floats)
#define PW   36     // packed bf16x2 word pitch
#define NS2  16     // softmax splits

typedef unsigned long long u64t;
typedef unsigned int u32;

// ---------------- scratch ----------------
__device__ float g_Qlm [BHN*64*64];
__device__ float g_KlmT[BHN*64*64];
__device__ float g_Klm [BHN*64*64];
__device__ float g_Inv [BHN*64*64];
__device__ float g_WT  [BHN*64*64];   // (inv@F)^T : [d][m]
__device__ float g_pacc[(size_t)NS2*BHN*64*64];
__device__ float g_psum[NS2*BHN*64];

// ---------------- scalar helpers ----------------
__device__ __forceinline__ u64t pk2(float lo, float hi) {
    u64t r; asm("mov.b64 %0, {%1, %2};" : "=l"(r) : "f"(lo), "f"(hi)); return r;
}
__device__ __forceinline__ u64t ffma2(u64t a, u64t b, u64t c) {
    u64t d; asm("fma.rn.f32x2 %0, %1, %2, %3;" : "=l"(d) : "l"(a), "l"(b), "l"(c)); return d;
}
__device__ __forceinline__ u32 bfpack(float x, float y) {
    __nv_bfloat162 h = __floats2bfloat162_rn(x, y);
    return *reinterpret_cast<u32*>(&h);
}
__device__ __forceinline__ void bfsplit(float x, float y, u32& hw, u32& lw) {
    __nv_bfloat162 h = __floats2bfloat162_rn(x, y);
    float hx = __bfloat162float(h.x), hy = __bfloat162float(h.y);
    hw = *reinterpret_cast<u32*>(&h);
    lw = bfpack(x - hx, y - hy);
}
__device__ __forceinline__ void mmab(float c[4], u32 a0, u32 a1, u32 a2, u32 a3,
                                     u32 b0, u32 b1) {
    asm volatile("mma.sync.aligned.m16n8k16.row.col.f32.bf16.bf16.f32 "
        "{%0,%1,%2,%3}, {%4,%5,%6,%7}, {%8,%9}, {%0,%1,%2,%3};"
        : "+f"(c[0]), "+f"(c[1]), "+f"(c[2]), "+f"(c[3])
        : "r"(a0), "r"(a1), "r"(a2), "r"(a3), "r"(b0), "r"(b1));
}
__device__ __forceinline__ u32 sptr(const void* p) {
    u32 a;
    asm("{ .reg .u64 t; cvta.to.shared.u64 t, %1; cvt.u32.u64 %0, t; }" : "=r"(a) : "l"(p));
    return a;
}
__device__ __forceinline__ void ldsm4(u32* r, u32 addr) {
    asm volatile("ldmatrix.sync.aligned.m8n8.x4.shared.b16 {%0,%1,%2,%3}, [%4];"
        : "=r"(r[0]), "=r"(r[1]), "=r"(r[2]), "=r"(r[3]) : "r"(addr));
}

// warp gemm: C[16x32] += A[16 rows, k=64] @ B[n = nbase..nbase+31, k=64]  (kc MMA1)
__device__ __forceinline__ void wg16x32(const u32* __restrict__ Ah, const u32* __restrict__ Al,
                                        int base,
                                        const u32* __restrict__ Bh, const u32* __restrict__ Bl,
                                        int nbase, int lane, float c[4][4]) {
    int mi = lane >> 3, lr = lane & 7;
    u32 aH = sptr(Ah + (base + (mi & 1)*8 + lr)*PW + (mi >> 1)*4);
    u32 aL = sptr(Al + (base + (mi & 1)*8 + lr)*PW + (mi >> 1)*4);
    u32 bH = sptr(Bh + (nbase + (mi >> 1)*8 + lr)*PW + (mi & 1)*4);
    u32 bL = sptr(Bl + (nbase + (mi >> 1)*8 + lr)*PW + (mi & 1)*4);
#pragma unroll
    for (int kt = 0; kt < 4; kt++) {
        u32 ah[4], al[4];
        ldsm4(ah, aH + kt*32);
        ldsm4(al, aL + kt*32);
#pragma unroll
        for (int p = 0; p < 2; p++) {
            u32 bh[4], bl[4];
            ldsm4(bh, bH + p*(16*PW*4) + kt*32);
            ldsm4(bl, bL + p*(16*PW*4) + kt*32);
            mmab(c[2*p],   ah[0],ah[1],ah[2],ah[3], bh[0],bh[1]);
            mmab(c[2*p],   al[0],al[1],al[2],al[3], bh[0],bh[1]);
            mmab(c[2*p],   ah[0],ah[1],ah[2],ah[3], bl[0],bl[1]);
            mmab(c[2*p+1], ah[0],ah[1],ah[2],ah[3], bh[2],bh[3]);
            mmab(c[2*p+1], al[0],al[1],al[2],al[3], bh[2],bh[3]);
            mmab(c[2*p+1], ah[0],ah[1],ah[2],ah[3], bl[2],bl[3]);
        }
    }
}

// MMA2 from register P (kc): d[16x64] += P(c regs, k=32) @ B[64 n, k=32 at word off co]
__device__ __forceinline__ void wg_regA_k32(const float c[4][4],
                                            const u32* __restrict__ Bh,
                                            const u32* __restrict__ Bl, int co,
                                            int lane, float d[8][4]) {
    int mi = lane >> 3, lr = lane & 7;
    u32 bH = sptr(Bh + ((mi >> 1)*8 + lr)*PW + (mi & 1)*4 + co);
    u32 bL = sptr(Bl + ((mi >> 1)*8 + lr)*PW + (mi & 1)*4 + co);
#pragma unroll
    for (int kt = 0; kt < 2; kt++) {
        u32 ah0, al0, ah1, al1, ah2, al2, ah3, al3;
        bfsplit(c[2*kt][0],   c[2*kt][1],   ah0, al0);
        bfsplit(c[2*kt][2],   c[2*kt][3],   ah1, al1);
        bfsplit(c[2*kt+1][0], c[2*kt+1][1], ah2, al2);
        bfsplit(c[2*kt+1][2], c[2*kt+1][3], ah3, al3);
#pragma unroll
        for (int p = 0; p < 4; p++) {
            u32 bh[4], bl[4];
            ldsm4(bh, bH + p*(16*PW*4) + kt*32);
            ldsm4(bl, bL + p*(16*PW*4) + kt*32);
            mmab(d[2*p],   ah0,ah1,ah2,ah3, bh[0],bh[1]);
            mmab(d[2*p],   al0,al1,al2,al3, bh[0],bh[1]);
            mmab(d[2*p],   ah0,ah1,ah2,ah3, bl[0],bl[1]);
            mmab(d[2*p+1], ah0,ah1,ah2,ah3, bh[2],bh[3]);
            mmab(d[2*p+1], al0,al1,al2,al3, bh[2],bh[3]);
            mmab(d[2*p+1], ah0,ah1,ah2,ah3, bl[2],bl[3]);
        }
    }
}

// MMA2 from register P (kd): d[16x64] += P(c regs, k=64) @ B[64 n, k=64]
__device__ __forceinline__ void wgemm16_regA(const float c[8][4],
                                             const u32* __restrict__ Bh,
                                             const u32* __restrict__ Bl,
                                             int lane, float d[8][4]) {
    int mi = lane >> 3, lr = lane & 7;
    u32 bH = sptr(Bh + ((mi >> 1)*8 + lr)*PW + (mi & 1)*4);
    u32 bL = sptr(Bl + ((mi >> 1)*8 + lr)*PW + (mi & 1)*4);
#pragma unroll
    for (int kt = 0; kt < 4; kt++) {
        u32 ah0, al0, ah1, al1, ah2, al2, ah3, al3;
        bfsplit(c[2*kt][0],   c[2*kt][1],   ah0, al0);
        bfsplit(c[2*kt][2],   c[2*kt][3],   ah1, al1);
        bfsplit(c[2*kt+1][0], c[2*kt+1][1], ah2, al2);
        bfsplit(c[2*kt+1][2], c[2*kt+1][3], ah3, al3);
#pragma unroll
        for (int p = 0; p < 4; p++) {
            u32 bh[4], bl[4];
            ldsm4(bh, bH + p*(16*PW*4) + kt*32);
            ldsm4(bl, bL + p*(16*PW*4) + kt*32);
            mmab(d[2*p],   ah0,ah1,ah2,ah3, bh[0],bh[1]);
            mmab(d[2*p],   al0,al1,al2,al3, bh[0],bh[1]);
            mmab(d[2*p],   ah0,ah1,ah2,ah3, bl[0],bl[1]);
            mmab(d[2*p+1], ah0,ah1,ah2,ah3, bh[2],bh[3]);
            mmab(d[2*p+1], al0,al1,al2,al3, bh[2],bh[3]);
            mmab(d[2*p+1], ah0,ah1,ah2,ah3, bl[2],bl[3]);
        }
    }
}

// kd MMA1: A fragments loaded directly from gmem (rows r0, r0+8), scale folded
__device__ __forceinline__ void wgemm16_gmemA(const float* __restrict__ qr0,
                                              const u32* __restrict__ Bh,
                                              const u32* __restrict__ Bl,
                                              int lane, float c[8][4]) {
    int t = lane & 3;
    int mi = lane >> 3, lr = lane & 7;
    u32 bH = sptr(Bh + ((mi >> 1)*8 + lr)*PW + (mi & 1)*4);
    u32 bL = sptr(Bl + ((mi >> 1)*8 + lr)*PW + (mi & 1)*4);
#pragma unroll
    for (int kt = 0; kt < 4; kt++) {
        const float* qp = qr0 + kt*16 + 2*t;
        float2 q00 = *(const float2*)(qp);
        float2 q20 = *(const float2*)(qp + 8);
        float2 q01 = *(const float2*)(qp + 512);       // row +8
        float2 q21 = *(const float2*)(qp + 520);
        u32 ah0, al0, ah1, al1, ah2, al2, ah3, al3;
        bfsplit(q00.x*0.125f, q00.y*0.125f, ah0, al0);
        bfsplit(q01.x*0.125f, q01.y*0.125f, ah1, al1);
        bfsplit(q20.x*0.125f, q20.y*0.125f, ah2, al2);
        bfsplit(q21.x*0.125f, q21.y*0.125f, ah3, al3);
#pragma unroll
        for (int p = 0; p < 4; p++) {
            u32 bh[4], bl[4];
            ldsm4(bh, bH + p*(16*PW*4) + kt*32);
            ldsm4(bl, bL + p*(16*PW*4) + kt*32);
            mmab(c[2*p],   ah0,ah1,ah2,ah3, bh[0],bh[1]);
            mmab(c[2*p],   al0,al1,al2,al3, bh[0],bh[1]);
            mmab(c[2*p],   ah0,ah1,ah2,ah3, bl[0],bl[1]);
            mmab(c[2*p+1], ah0,ah1,ah2,ah3, bh[2],bh[3]);
            mmab(c[2*p+1], al0,al1,al2,al3, bh[2],bh[3]);
            mmab(c[2*p+1], ah0,ah1,ah2,ah3, bl[2],bl[3]);
        }
    }
}

// stage row-major fp32 [rows][64] -> packed along k
__device__ __forceinline__ void stage_k(u32* Dh, u32* Dl, const float* __restrict__ src,
                                        int rows, int tid, int nthr, float scale) {
    for (int f = tid; f < rows*16; f += nthr) {
        int r = f >> 4, q = f & 15;
        float4 v = *(const float4*)(src + r*64 + 4*q);
        v.x *= scale; v.y *= scale; v.z *= scale; v.w *= scale;
        u32 h0, l0, h1, l1;
        bfsplit(v.x, v.y, h0, l0);
        bfsplit(v.z, v.w, h1, l1);
        *(u64t*)(Dh + r*PW + 2*q) = (u64t)h0 | ((u64t)h1 << 32);
        *(u64t*)(Dl + r*PW + 2*q) = (u64t)l0 | ((u64t)l1 << 32);
    }
}

// stage V [64 s][64 d] -> packed along s
__device__ __forceinline__ void stage_v(u32* Dh, u32* Dl, const float* __restrict__ src,
                                        int tid, int nthr) {
    for (int f = tid; f < 512; f += nthr) {
        int c = f & 63, grp = f >> 6;
        int s0 = grp*8;
        float v[8];
#pragma unroll
        for (int j = 0; j < 8; j++) v[j] = src[(s0+j)*64 + c];
        u32 h[4], l[4];
#pragma unroll
        for (int i = 0; i < 4; i++) bfsplit(v[2*i], v[2*i+1], h[i], l[i]);
        *(uint4*)(Dh + c*PW + 4*grp) = make_uint4(h[0], h[1], h[2], h[3]);
        *(uint4*)(Dl + c*PW + 4*grp) = make_uint4(l[0], l[1], l[2], l[3]);
    }
}

// ---------------- plain FFMA2 64x64 matmul core ----------------
__device__ __forceinline__ void mm64_core(const float* __restrict__ A,
                                          const float* __restrict__ B,
                                          int rq, int cq, u64t acc[4][2]) {
#pragma unroll
    for (int k = 0; k < 64; k++) {
        u64t b0 = *(const u64t*)(B + k*PB + 2*cq);
        u64t b1 = *(const u64t*)(B + k*PB + 2*cq + 32);
#pragma unroll
        for (int r = 0; r < 4; r++) {
            float a = A[(rq + 16*r)*PB + k];
            u64t a2 = pk2(a, a);
            acc[r][0] = ffma2(a2, b0, acc[r][0]);
            acc[r][1] = ffma2(a2, b1, acc[r][1]);
        }
    }
}
__device__ __noinline__ void mm64_smem(const float* __restrict__ A,
                                       const float* __restrict__ B,
                                       float* __restrict__ C, int tid) {
    int cq = tid & 15, rq = tid >> 4;
    u64t acc[4][2] = {};
    mm64_core(A, B, rq, cq, acc);
#pragma unroll
    for (int r = 0; r < 4; r++) {
        *(u64t*)(C + (rq+16*r)*PB + 2*cq)      = acc[r][0];
        *(u64t*)(C + (rq+16*r)*PB + 2*cq + 32) = acc[r][1];
    }
}
__device__ __forceinline__ void tr_write(float* Ct, int rq, int cq, float aI, float bS,
                                         const u64t acc[4][2]) {
    int j0 = 2*cq, j2 = 2*cq + 32;
#pragma unroll
    for (int r = 0; r < 4; r++) {
        int row = rq + 16*r;
        float v0, v1, v2, v3;
        asm("mov.b64 {%0, %1}, %2;" : "=f"(v0), "=f"(v1) : "l"(acc[r][0]));
        asm("mov.b64 {%0, %1}, %2;" : "=f"(v2), "=f"(v3) : "l"(acc[r][1]));
        float t0 = (row == j0   ? aI : 0.f) - bS*v0;
        float t1 = (row == j0+1 ? aI : 0.f) - bS*v1;
        float t2 = (row == j2   ? aI : 0.f) - bS*v2;
        float t3 = (row == j2+1 ? aI : 0.f) - bS*v3;
        *(u64t*)(Ct + row*PB + j0) = pk2(t0, t1);
        *(u64t*)(Ct + row*PB + j2) = pk2(t2, t3);
    }
}
__device__ __forceinline__ void raw_write(float* C, int rq, int cq, const u64t acc[4][2]) {
#pragma unroll
    for (int r = 0; r < 4; r++) {
        int row = rq + 16*r;
        *(u64t*)(C + row*PB + 2*cq)      = acc[r][0];
        *(u64t*)(C + row*PB + 2*cq + 32) = acc[r][1];
    }
}

// ---------------- pooling (float4 loads) ----------------
__global__ void __launch_bounds__(256) pool_kernel(const float* __restrict__ Q,
                                                   const float* __restrict__ K) {
    int bh = blockIdx.x >> 6, lm = blockIdx.x & 63;
    int tid = threadIdx.x;
    int q = tid & 15, rg = tid >> 4;
    const float* qb = Q + ((size_t)bh*SQ + lm*64)*64;
    const float* kb = K + ((size_t)bh*SQ + lm*64)*64;
    float4 sq = {0.f,0.f,0.f,0.f}, sk = {0.f,0.f,0.f,0.f};
#pragma unroll
    for (int r = rg; r < 64; r += 16) {
        float4 a = *(const float4*)(qb + r*64 + 4*q);
        float4 b = *(const float4*)(kb + r*64 + 4*q);
        sq.x += a.x; sq.y += a.y; sq.z += a.z; sq.w += a.w;
        sk.x += b.x; sk.y += b.y; sk.z += b.z; sk.w += b.w;
    }
    __shared__ float4 shq[16][16], shk[16][16];
    shq[rg][q] = sq; shk[rg][q] = sk;
    __syncthreads();
    if (tid < 64) {
        int d = tid, qq = d >> 2, cc = d & 3;
        float s1 = 0.f, s2 = 0.f;
#pragma unroll
        for (int i = 0; i < 16; i++) {
            s1 += ((const float*)&shq[i][qq])[cc];
            s2 += ((const float*)&shk[i][qq])[cc];
        }
        float qv = s1 * (1.0f/512.0f);
        float kv = s2 * (1.0f/64.0f);
        g_Qlm [bh*4096 + lm*64 + d] = qv;
        g_Klm [bh*4096 + lm*64 + d] = kv;
        g_KlmT[bh*4096 + d*64 + lm] = kv;
    }
}

// ---------------- Newton-Schulz body: 4 buffers, exact fp32 trajectory ----------------
__device__ void newton_body(float* sm, int bh) {
    float* A = sm;
    float* X = sm + 1*64*PB;
    float* Y = sm + 2*64*PB;
    float* Z = sm + 3*64*PB;
    __shared__ float nsred[256], nsrow[64], nscol[64], nscale[1];
    int tid = threadIdx.x;
    int cq = tid & 15, rq = tid >> 4;

    for (int idx = tid; idx < 4096; idx += 256) {
        int i = idx >> 6, k = idx & 63;
        Y[i*PB + k] = g_Qlm[bh*4096 + idx];
        Z[i*PB + k] = g_KlmT[bh*4096 + idx];
    }
    __syncthreads();
    mm64_smem(Y, Z, A, tid);
    __syncthreads();
    {
        int q = tid & 3, r = tid >> 2;
        float* Lr = A + r*PB + q*16;
        float mt = Lr[0];
#pragma unroll
        for (int c = 1; c < 16; c++) mt = fmaxf(mt, Lr[c]);
        nsred[tid] = mt; __syncthreads();
        float m = fmaxf(fmaxf(nsred[r*4], nsred[r*4+1]), fmaxf(nsred[r*4+2], nsred[r*4+3]));
        float ps = 0.f;
#pragma unroll
        for (int c = 0; c < 16; c++) { float e = __expf(Lr[c] - m); Lr[c] = e; ps += e; }
        __syncthreads();
        nsred[tid] = ps; __syncthreads();
        float inv = 1.0f / (nsred[r*4] + nsred[r*4+1] + nsred[r*4+2] + nsred[r*4+3]);
#pragma unroll
        for (int c = 0; c < 16; c++) Lr[c] *= inv;
    }
    __syncthreads();
    if (tid < 64)       { float s = 0.f; for (int j = 0; j < 64; j++) s += A[tid*PB + j]; nsrow[tid] = s; }
    else if (tid < 128) { int c = tid - 64; float s = 0.f; for (int i = 0; i < 64; i++) s += A[i*PB + c]; nscol[c] = s; }
    __syncthreads();
    if (tid == 0) {
        float mr = nsrow[0], mc = nscol[0];
        for (int i = 1; i < 64; i++) { mr = fmaxf(mr, nsrow[i]); mc = fmaxf(mc, nscol[i]); }
        nscale[0] = 1.0f / (mr * mc);
    }
    __syncthreads();
    float sc = nscale[0];
    for (int idx = tid; idx < 4096; idx += 256) {
        int i = idx >> 6, j = idx & 63;
        X[j*PB + i] = A[i*PB + j] * sc;
    }
    __syncthreads();

    float *Vb = X, *F1 = Y, *F2 = Z;
#pragma unroll 1
    for (int it = 0; it < 6; it++) {
        {
            u64t acc[4][2] = {};
            mm64_core(A, Vb, rq, cq, acc);
            raw_write(F1, rq, cq, acc);
            tr_write(F2, rq, cq, 7.0f, 1.0f, acc);
        }
        __syncthreads();
        {
            u64t acc[4][2] = {};
            mm64_core(F1, F2, rq, cq, acc);
            __syncthreads();
            tr_write(F2, rq, cq, 15.0f, 1.0f, acc);
        }
        __syncthreads();
        {
            u64t acc[4][2] = {};
            mm64_core(F1, F2, rq, cq, acc);
            __syncthreads();
            tr_write(F1, rq, cq, 3.25f, 0.25f, acc);
        }
        __syncthreads();
        {
            u64t acc[4][2] = {};
            mm64_core(Vb, F1, rq, cq, acc);
            raw_write(F2, rq, cq, acc);
        }
        __syncthreads();
        float* nv = F2; F2 = F1; F1 = Vb; Vb = nv;
    }
    for (int idx = tid; idx < 4096; idx += 256) {
        int i = idx >> 6, j = idx & 63;
        g_Inv[bh*4096 + idx] = Vb[i*PB + j];
    }
}

// ---------------- kc body: 8 warps share one K/V tile; halves merged in-block ----------------
__device__ void kc_body(const float* __restrict__ K, const float* __restrict__ V,
                        u32* sm, int sp, int bh) {
    u32* Qlh = sm;
    u32* Qll = sm + 64*PW;
    u32* Kh  = sm + 2*64*PW;
    u32* Kl  = sm + 3*64*PW;
    u32* Vh  = sm + 4*64*PW;
    u32* Vl  = sm + 5*64*PW;
    float* xch = (float*)(sm + 2*64*PW);   // reuse K region for epilogue merge
    __shared__ float srs[4][16];
    int tid = threadIdx.x, lane = tid & 31, wid = tid >> 5;
    int g = lane >> 2, t = lane & 3;
    int wd = wid & 3, half = wid >> 2;
    int base = wd*16, nb = half*32, co = half*16;

    stage_k(Qlh, Qll, g_Qlm + bh*4096, 64, tid, 256, 1.0f);   // already *0.125

    float acc[8][4] = {};
    float rs0 = 0.f, rs1 = 0.f;
    __syncthreads();

#pragma unroll 1
    for (int it = 0; it < 4; it++) {
        int s0 = sp*256 + it*64;
        stage_k(Kh, Kl, K + ((size_t)bh*SQ + s0)*64, 64, tid, 256, 1.0f);
        stage_v(Vh, Vl, V + ((size_t)bh*SQ + s0)*64, tid, 256);
        __syncthreads();

        float c[4][4] = {};
        wg16x32(Qlh, Qll, base, Kh, Kl, nb, lane, c);   // logits[16 lm][32 s-half]

#pragma unroll
        for (int n = 0; n < 4; n++) {
            c[n][0] = __expf(c[n][0]); c[n][1] = __expf(c[n][1]);
            c[n][2] = __expf(c[n][2]); c[n][3] = __expf(c[n][3]);
            rs0 += c[n][0] + c[n][1];
            rs1 += c[n][2] + c[n][3];
        }
        wg_regA_k32(c, Vh, Vl, co, lane, acc);          // acc += P @ V(s-half), full d
        __syncthreads();                                // K/V reads done before restage
    }

    rs0 += __shfl_xor_sync(0xffffffffu, rs0, 1);
    rs0 += __shfl_xor_sync(0xffffffffu, rs0, 2);
    rs1 += __shfl_xor_sync(0xffffffffu, rs1, 1);
    rs1 += __shfl_xor_sync(0xffffffffu, rs1, 2);

    int r0 = base + g;
    if (half == 1) {
#pragma unroll
        for (int nt = 0; nt < 8; nt++) {
            int col = 8*nt + 2*t;
            *(float2*)(xch + r0*64 + col)     = make_float2(acc[nt][0], acc[nt][1]);
            *(float2*)(xch + (r0+8)*64 + col) = make_float2(acc[nt][2], acc[nt][3]);
        }
        if (t == 0) { srs[wd][g] = rs0; srs[wd][g + 8] = rs1; }
    }
    __syncthreads();
    if (half == 0) {
        size_t pb = ((size_t)sp*BHN + bh)*4096;
#pragma unroll
        for (int nt = 0; nt < 8; nt++) {
            int col = 8*nt + 2*t;
            float2 oA = *(const float2*)(xch + r0*64 + col);
            float2 oB = *(const float2*)(xch + (r0+8)*64 + col);
            *(float2*)(g_pacc + pb + r0*64 + col) =
                make_float2(acc[nt][0] + oA.x, acc[nt][1] + oA.y);
            *(float2*)(g_pacc + pb + (r0+8)*64 + col) =
                make_float2(acc[nt][2] + oB.x, acc[nt][3] + oB.y);
        }
        if (t == 0) {
            float* ps = g_psum + (sp*BHN + bh)*64;
            ps[r0]     = rs0 + srs[wd][g];
            ps[r0 + 8] = rs1 + srs[wd][g + 8];
        }
    }
}

__global__ void __launch_bounds__(256, 3) mega_kernel(const float* __restrict__ K,
                                                      const float* __restrict__ V) {
    extern __shared__ __align__(16) u32 smg[];
    if (blockIdx.x < 64) newton_body((float*)smg, blockIdx.x);
    else { int id = blockIdx.x - 64; kc_body(K, V, smg, id & (NS2-1), id >> 4); }
}

// ---------------- reduce splits -> F-quarter, W-quarter = Inv@Fq, store W^T ----------------
__global__ void __launch_bounds__(256) reduce_winv_kernel() {
    __shared__ float Fs[64][17];
    __shared__ float Iv[64*PB];
    int dq = blockIdx.x, bh = blockIdx.y, tid = threadIdx.x;

    for (int idx = tid; idx < 4096; idx += 256)
        Iv[(idx>>6)*PB + (idx&63)] = g_Inv[bh*4096 + idx];

    // F quarter: 64 rows x 16 d-cols
    for (int f = tid; f < 1024; f += 256) {
        int i = f >> 4, dc = f & 15;
        int d = dq*16 + dc;
        float tot = 0.f, v = 0.f;
#pragma unroll
        for (int s = 0; s < NS2; s++) {
            tot += g_psum[(s*BHN+bh)*64 + i];
            v   += g_pacc[((size_t)s*BHN+bh)*4096 + i*64 + d];
        }
        Fs[i][dc] = v / tot;
    }
    __syncthreads();

    // W quarter: W[m][d] = sum_k Inv[m][k] * Fq[k][dc]; store transposed
    int dc = tid & 15, m0 = tid >> 4;
    float* wt = g_WT + (size_t)bh*4096 + (dq*16 + dc)*64;
#pragma unroll
    for (int r = 0; r < 4; r++) {
        int m = m0 + 16*r;
        float w = 0.f;
#pragma unroll
        for (int k = 0; k < 64; k++) w += Iv[m*PB + k] * Fs[k][dc];
        wt[m] = w;
    }
}

// ---------------- kd: 8 warps, M=16/warp, Q direct from gmem, P in regs, 4 tiles ----------------
__global__ void __launch_bounds__(256, 3) kd_bf(const float* __restrict__ Q,
                                                float* __restrict__ X) {
    extern __shared__ __align__(16) u32 smk[];
    u32* Kh = smk;
    u32* Kl = Kh + 64*PW;
    u32* Wh = Kl + 64*PW;
    u32* Wl = Wh + 64*PW;
    int tid = threadIdx.x, lane = tid & 31, wid = tid >> 5;
    int g = lane >> 2, t = lane & 3;
    int bh = blockIdx.y;

    stage_k(Kh, Kl, g_Klm + (size_t)bh*4096, 64, tid, 256, 1.0f);
    stage_k(Wh, Wl, g_WT  + (size_t)bh*4096, 64, tid, 256, 1.0f);
    __syncthreads();

    int base = wid*16;
    int r0 = base + g;

#pragma unroll 1
    for (int t2 = 0; t2 < 4; t2++) {
        int tile = blockIdx.x*4 + t2;
        const float* qr0 = Q + ((size_t)bh*SQ + tile*128 + r0)*64;

        float c[8][4];
#pragma unroll
        for (int n = 0; n < 8; n++) { c[n][0]=0.f; c[n][1]=0.f; c[n][2]=0.f; c[n][3]=0.f; }
        wgemm16_gmemA(qr0, Kh, Kl, lane, c);      // logits [tok][lm], Q from gmem

        float rs0 = 0.f, rs1 = 0.f;
#pragma unroll
        for (int n = 0; n < 8; n++) {
            c[n][0] = __expf(c[n][0]); c[n][1] = __expf(c[n][1]);
            c[n][2] = __expf(c[n][2]); c[n][3] = __expf(c[n][3]);
            rs0 += c[n][0] + c[n][1];
            rs1 += c[n][2] + c[n][3];
        }
        rs0 += __shfl_xor_sync(0xffffffffu, rs0, 1);
        rs0 += __shfl_xor_sync(0xffffffffu, rs0, 2);
        rs1 += __shfl_xor_sync(0xffffffffu, rs1, 1);
        rs1 += __shfl_xor_sync(0xffffffffu, rs1, 2);
        float rinv0 = 1.0f / rs0, rinv1 = 1.0f / rs1;

        float d[8][4];
#pragma unroll
        for (int n = 0; n < 8; n++) { d[n][0]=0.f; d[n][1]=0.f; d[n][2]=0.f; d[n][3]=0.f; }
        wgemm16_regA(c, Wh, Wl, lane, d);         // X~ = P @ W (P from regs)

        float* x0 = X + ((size_t)bh*SQ + tile*128)*64;
#pragma unroll
        for (int nt = 0; nt < 8; nt++) {
            int col = 8*nt + 2*t;
            *(float2*)(x0 + r0*64 + col)     = make_float2(d[nt][0]*rinv0, d[nt][1]*rinv0);
            *(float2*)(x0 + (r0+8)*64 + col) = make_float2(d[nt][2]*rinv1, d[nt][3]*rinv1);
        }
    }
}

// ---------------- launcher ----------------
extern "C" void kernel_launch(void* const* d_in, const int* in_sizes, int n_in,
                              void* d_out, int out_size) {
    (void)in_sizes; (void)n_in; (void)out_size;
    const float* Q = (const float*)d_in[0];
    const float* K = (const float*)d_in[1];
    const float* V = (const float*)d_in[2];
    float* X = (float*)d_out;

    const int SMEM_MEGA = 4*64*PB*4;    // 69632 (newton); kc uses 55296 -> 3 CTAs/SM
    const int SMEM_KD   = 4*64*PW*4;    // 36864
    cudaFuncSetAttribute(mega_kernel, cudaFuncAttributeMaxDynamicSharedMemorySize, SMEM_MEGA);
    cudaFuncSetAttribute(kd_bf,       cudaFuncAttributeMaxDynamicSharedMemorySize, SMEM_KD);

    pool_kernel<<<BHN*64, 256>>>(Q, K);
    mega_kernel<<<64 + NS2*BHN, 256, SMEM_MEGA>>>(K, V);
    reduce_winv_kernel<<<dim3(4, BHN), 256>>>();
    kd_bf<<<dim3(8, BHN), 256, SMEM_KD>>>(Q, X);
}